// round 1
// baseline (speedup 1.0000x reference)
#include <cuda_runtime.h>
#include <math.h>

#define T 8
#define N 2048
#define F 128
#define C 64

// ---------------- device scratch (static, no allocations) ----------------
__device__ float g_h[T * N * C];          // 4 MB   h = x @ W
__device__ float g_es[T * N];             // e_s
__device__ float g_ed[T * N];             // e_d
__device__ float g_out[T * N * C];        // 4 MB   GAT output (pre-temporal)
__device__ float g_tem[(T - 1) * N];      // cosine similarities
__device__ float g_pacc[2][T * N * C];    // 8 MB   j-split partial accumulators
__device__ float g_psum[2][T * N];        // j-split partial softmax sums

// ---------------- f32x2 helpers ----------------
__device__ __forceinline__ unsigned long long pk2(float lo, float hi) {
    unsigned long long r;
    asm("mov.b64 %0, {%1, %2};" : "=l"(r) : "f"(lo), "f"(hi));
    return r;
}
__device__ __forceinline__ void upk2(unsigned long long v, float& lo, float& hi) {
    asm("mov.b64 {%0, %1}, %2;" : "=f"(lo), "=f"(hi) : "l"(v));
}
__device__ __forceinline__ void fma2(unsigned long long& d, unsigned long long a,
                                     unsigned long long b) {
    asm("fma.rn.f32x2 %0, %1, %2, %0;" : "+l"(d) : "l"(a), "l"(b));
}

// ============================================================
// Kernel A: h = x @ W  (+ e_s = h.a_src, e_d = h.a_dst)
// block = 128 threads, 32 rows x 4 c-groups of 16
// ============================================================
__global__ __launch_bounds__(128) void kA(const float* __restrict__ x,
                                          const float* __restrict__ W,
                                          const float* __restrict__ asrc,
                                          const float* __restrict__ adst) {
    __shared__ __align__(16) float ws[F * C];   // 32 KB
    int tid = threadIdx.x;
    int t = blockIdx.y;
    int n0 = blockIdx.x * 32;

    // load W (8192 floats = 2048 float4)
    const float4* wg = (const float4*)W;
    float4* ws4 = (float4*)ws;
#pragma unroll
    for (int r = 0; r < 16; r++) ws4[tid + r * 128] = wg[tid + r * 128];
    __syncthreads();

    int row = tid >> 2;
    int cg = (tid & 3) * 16;
    int n = n0 + row;
    const float* xrow = x + ((size_t)t * N + n) * F;

    unsigned long long acc2[8];
#pragma unroll
    for (int q = 0; q < 8; q++) acc2[q] = 0ull;

#pragma unroll 4
    for (int k = 0; k < F; k += 4) {
        float4 xq = *(const float4*)(xrow + k);
        float xv[4] = {xq.x, xq.y, xq.z, xq.w};
#pragma unroll
        for (int s = 0; s < 4; s++) {
            unsigned long long pp = pk2(xv[s], xv[s]);
            const ulonglong2* wr = (const ulonglong2*)(ws + (k + s) * C + cg);
#pragma unroll
            for (int q = 0; q < 4; q++) {
                ulonglong2 wv = wr[q];
                fma2(acc2[2 * q], wv.x, pp);
                fma2(acc2[2 * q + 1], wv.y, pp);
            }
        }
    }

    float hc[16];
#pragma unroll
    for (int q = 0; q < 8; q++) upk2(acc2[q], hc[2 * q], hc[2 * q + 1]);

    // write h
    float4* hg = (float4*)(g_h + ((size_t)t * N + n) * C + cg);
#pragma unroll
    for (int q = 0; q < 4; q++)
        hg[q] = make_float4(hc[q * 4], hc[q * 4 + 1], hc[q * 4 + 2], hc[q * 4 + 3]);

    // e_s / e_d partial dot, reduce across the 4 c-groups (adjacent lanes)
    float es = 0.f, ed = 0.f;
#pragma unroll
    for (int c = 0; c < 16; c++) {
        es = fmaf(hc[c], asrc[cg + c], es);
        ed = fmaf(hc[c], adst[cg + c], ed);
    }
    es += __shfl_down_sync(0xffffffffu, es, 1, 4);
    es += __shfl_down_sync(0xffffffffu, es, 2, 4);
    ed += __shfl_down_sync(0xffffffffu, ed, 1, 4);
    ed += __shfl_down_sync(0xffffffffu, ed, 2, 4);
    if ((tid & 3) == 0) {
        g_es[t * N + n] = es;
        g_ed[t * N + n] = ed;
    }
}

// ============================================================
// Kernel B: masked softmax aggregation  out_i = sum_j p_ij h_j
// One thread per destination node i (256 i per block), j split in halves.
// Single-pass softmax using the global upper bound M_i.
// ============================================================
__global__ __launch_bounds__(256) void kB(const int* __restrict__ adj) {
    __shared__ float es_sm[N];                       // 8 KB
    __shared__ __align__(16) float hs[32 * C];       // 8 KB
    __shared__ unsigned char ms[32 * 256];           // 8 KB
    __shared__ float red[256];

    int tid = threadIdx.x;
    int t = blockIdx.y;
    int itile = blockIdx.x >> 1;
    int jh = blockIdx.x & 1;
    int i0 = itile * 256;
    int i = i0 + tid;

    // stage e_s for the whole graph + block-wide max
    float lmax = -1e30f;
#pragma unroll
    for (int r = 0; r < 8; r++) {
        float v = g_es[t * N + tid + r * 256];
        es_sm[tid + r * 256] = v;
        lmax = fmaxf(lmax, v);
    }
    red[tid] = lmax;
    __syncthreads();
    for (int s = 128; s > 0; s >>= 1) {
        if (tid < s) red[tid] = fmaxf(red[tid], red[tid + s]);
        __syncthreads();
    }
    float esmax = red[0];

    float ed_i = g_ed[t * N + i];
    float xm = ed_i + esmax;
    float M = fmaxf(xm, 0.2f * xm);  // lrelu is monotone -> valid upper bound

    unsigned long long acc[32];
#pragma unroll
    for (int k = 0; k < 32; k++) acc[k] = 0ull;
    float ssum = 0.f;

    int jbeg = jh * (N / 2), jend = jbeg + (N / 2);
    const float* hbase = g_h + (size_t)t * N * C;
    const int* abase = adj + (size_t)t * N * N + i0;

    for (int j0 = jbeg; j0 < jend; j0 += 32) {
        __syncthreads();
        // h tile: 32 rows x 64 c = 512 float4
        const float4* hg = (const float4*)(hbase + (size_t)j0 * C);
        ((float4*)hs)[tid] = hg[tid];
        ((float4*)hs)[tid + 256] = hg[tid + 256];
        // adj tile: [32 j][256 i] ints -> byte mask (coalesced in i)
#pragma unroll
        for (int r = 0; r < 8; r++) {
            int idx4 = tid + r * 256;
            int rw = idx4 >> 6, c4 = idx4 & 63;
            int4 v = *(const int4*)(abase + (size_t)(j0 + rw) * N + c4 * 4);
            unsigned char* mp = &ms[rw * 256 + c4 * 4];
            mp[0] = (v.x != 0);
            mp[1] = (v.y != 0);
            mp[2] = (v.z != 0);
            mp[3] = (v.w != 0);
        }
        __syncthreads();

#pragma unroll 4
        for (int jj = 0; jj < 32; jj++) {
            int j = j0 + jj;
            float e = ed_i + es_sm[j];
            float l = fmaxf(e, 0.2f * e);
            float p = __expf(l - M);
            bool mk = (ms[jj * 256 + tid] != 0) | (j == i);
            p = mk ? p : 0.f;
            ssum += p;
            unsigned long long pp = pk2(p, p);
            const ulonglong2* hr = (const ulonglong2*)(hs + jj * C);
#pragma unroll
            for (int k = 0; k < 16; k++) {
                ulonglong2 hv = hr[k];
                fma2(acc[2 * k], hv.x, pp);
                fma2(acc[2 * k + 1], hv.y, pp);
            }
        }
    }

    float* pa = g_pacc[jh] + ((size_t)(t * N + i)) * C;
#pragma unroll
    for (int k = 0; k < 16; k++) {
        ulonglong2 v;
        v.x = acc[2 * k];
        v.y = acc[2 * k + 1];
        ((ulonglong2*)pa)[k] = v;
    }
    g_psum[jh][t * N + i] = ssum;
}

// ============================================================
// Kernel B2: combine j-split partials, divide, add bias -> g_out
// ============================================================
__global__ __launch_bounds__(256) void kB2(const float* __restrict__ bias) {
    int idx = blockIdx.x * 256 + threadIdx.x;  // over T*N*C/4 float4
    int row = idx >> 4;
    int c4 = idx & 15;
    float s = g_psum[0][row] + g_psum[1][row];
    float inv = 1.f / s;
    float4 a = ((const float4*)g_pacc[0])[idx];
    float4 b = ((const float4*)g_pacc[1])[idx];
    float4 bb = ((const float4*)bias)[c4];
    float4 o;
    o.x = (a.x + b.x) * inv + bb.x;
    o.y = (a.y + b.y) * inv + bb.y;
    o.z = (a.z + b.z) * inv + bb.z;
    o.w = (a.w + b.w) * inv + bb.w;
    ((float4*)g_out)[idx] = o;
}

// ============================================================
// Kernel C1: tem[t,n] = cos_sim(out[t,n], out[t+1,n])  (warp per row)
// ============================================================
__global__ __launch_bounds__(256) void kC1() {
    int w = (blockIdx.x * 256 + threadIdx.x) >> 5;
    int lane = threadIdx.x & 31;
    if (w >= (T - 1) * N) return;
    int t = w / N, n = w % N;
    const float2* A = (const float2*)(g_out + ((size_t)t * N + n) * C);
    const float2* B = (const float2*)(g_out + ((size_t)(t + 1) * N + n) * C);
    float2 a = A[lane], b = B[lane];
    float dot = a.x * b.x + a.y * b.y;
    float na = a.x * a.x + a.y * a.y;
    float nb = b.x * b.x + b.y * b.y;
#pragma unroll
    for (int off = 16; off > 0; off >>= 1) {
        dot += __shfl_xor_sync(0xffffffffu, dot, off);
        na += __shfl_xor_sync(0xffffffffu, na, off);
        nb += __shfl_xor_sync(0xffffffffu, nb, off);
    }
    if (lane == 0) {
        float d1 = fmaxf(sqrtf(na), 1e-8f);
        float d2 = fmaxf(sqrtf(nb), 1e-8f);
        g_tem[w] = dot / (d1 * d2);
    }
}

// ============================================================
// Kernel C2: final = out + [t>=1](tem[t-1]*out[t-1])@t2w
//                        + [t<7](tem[t]*out[t+1])@t1w
// block: (t, 32 nodes), thread = (node, 8 output dims)
// ============================================================
__global__ __launch_bounds__(256) void kC2(const float* __restrict__ t1w,
                                           const float* __restrict__ t2w,
                                           float* __restrict__ out) {
    __shared__ __align__(16) float w1[C * C];  // 16 KB
    __shared__ __align__(16) float w2[C * C];  // 16 KB
    int tid = threadIdx.x;
    int t = blockIdx.y;
    int n0 = blockIdx.x * 32;
#pragma unroll
    for (int r = 0; r < 4; r++) {
        ((float4*)w1)[tid + r * 256] = ((const float4*)t1w)[tid + r * 256];
        ((float4*)w2)[tid + r * 256] = ((const float4*)t2w)[tid + r * 256];
    }
    __syncthreads();

    int nl = tid >> 3;
    int dg = (tid & 7) * 8;
    int n = n0 + nl;
    size_t rowo = ((size_t)t * N + n) * C;

    float r[8];
#pragma unroll
    for (int q = 0; q < 2; q++) {
        float4 v = *(const float4*)(g_out + rowo + dg + q * 4);
        r[q * 4] = v.x;
        r[q * 4 + 1] = v.y;
        r[q * 4 + 2] = v.z;
        r[q * 4 + 3] = v.w;
    }

    if (t < T - 1) {
        float tm = g_tem[t * N + n];
        const float* bro = g_out + ((size_t)(t + 1) * N + n) * C;
        for (int c = 0; c < C; c += 4) {
            float4 bv = *(const float4*)(bro + c);
            float u[4] = {tm * bv.x, tm * bv.y, tm * bv.z, tm * bv.w};
#pragma unroll
            for (int s = 0; s < 4; s++) {
                const float* wr = w1 + (c + s) * C + dg;
#pragma unroll
                for (int d = 0; d < 8; d++) r[d] = fmaf(u[s], wr[d], r[d]);
            }
        }
    }
    if (t >= 1) {
        float tm = g_tem[(t - 1) * N + n];
        const float* aro = g_out + ((size_t)(t - 1) * N + n) * C;
        for (int c = 0; c < C; c += 4) {
            float4 av = *(const float4*)(aro + c);
            float u[4] = {tm * av.x, tm * av.y, tm * av.z, tm * av.w};
#pragma unroll
            for (int s = 0; s < 4; s++) {
                const float* wr = w2 + (c + s) * C + dg;
#pragma unroll
                for (int d = 0; d < 8; d++) r[d] = fmaf(u[s], wr[d], r[d]);
            }
        }
    }

#pragma unroll
    for (int q = 0; q < 2; q++) {
        *(float4*)(out + rowo + dg + q * 4) =
            make_float4(r[q * 4], r[q * 4 + 1], r[q * 4 + 2], r[q * 4 + 3]);
    }
}

// ============================================================
extern "C" void kernel_launch(void* const* d_in, const int* in_sizes, int n_in,
                              void* d_out, int out_size) {
    const float* x = (const float*)d_in[0];
    const int* adj = (const int*)d_in[1];
    const float* W = (const float*)d_in[2];
    const float* asrc = (const float*)d_in[3];
    const float* adst = (const float*)d_in[4];
    const float* bias = (const float*)d_in[5];
    const float* t1w = (const float*)d_in[6];
    const float* t2w = (const float*)d_in[7];
    float* out = (float*)d_out;

    kA<<<dim3(N / 32, T), 128>>>(x, W, asrc, adst);
    kB<<<dim3(16, T), 256>>>(adj);
    kB2<<<(T * N * C / 4) / 256, 256>>>(bias);
    kC1<<<((T - 1) * N * 32 + 255) / 256, 256>>>();
    kC2<<<dim3(N / 32, T), 256>>>(t1w, t2w, out);
}

// round 4
// speedup vs baseline: 1.6519x; 1.6519x over previous
#include <cuda_runtime.h>
#include <cuda_bf16.h>
#include <math.h>
#include <stdint.h>

#define T 8
#define N 2048
#define F 128
#define C 64

// ---------------- device scratch ----------------
__device__ float g_es[T * N];
__device__ float g_ed[T * N];
__device__ float g_out[T * N * C];
__device__ float g_tem[(T - 1) * N];
__device__ __nv_bfloat16 g_hThi[T * C * N];   // h transposed hi bf16: [t][c][n]
__device__ __nv_bfloat16 g_hTlo[T * C * N];   // residual lo bf16

// ---------------- helpers ----------------
__device__ __forceinline__ uint32_t smem_u32(const void* p) {
    uint32_t a;
    asm("{ .reg .u64 t; cvta.to.shared.u64 t, %1; cvt.u32.u64 %0, t; }"
        : "=r"(a) : "l"(p));
    return a;
}
#define CP_ASYNC16(dst, src) \
    asm volatile("cp.async.cg.shared.global [%0], [%1], 16;" :: "r"(dst), "l"(src) : "memory")
#define CP_COMMIT() asm volatile("cp.async.commit_group;" ::: "memory")
#define CP_WAIT0() asm volatile("cp.async.wait_group 0;" ::: "memory")

__device__ __forceinline__ void ldsm4(uint32_t& r0, uint32_t& r1, uint32_t& r2,
                                      uint32_t& r3, uint32_t addr) {
    asm volatile("ldmatrix.sync.aligned.m8n8.x4.shared.b16 {%0,%1,%2,%3}, [%4];"
                 : "=r"(r0), "=r"(r1), "=r"(r2), "=r"(r3) : "r"(addr));
}
__device__ __forceinline__ void mma16816(float* d, const uint32_t* a, uint32_t b0,
                                         uint32_t b1) {
    asm volatile(
        "mma.sync.aligned.m16n8k16.row.col.f32.bf16.bf16.f32 "
        "{%0,%1,%2,%3}, {%4,%5,%6,%7}, {%8,%9}, {%0,%1,%2,%3};"
        : "+f"(d[0]), "+f"(d[1]), "+f"(d[2]), "+f"(d[3])
        : "r"(a[0]), "r"(a[1]), "r"(a[2]), "r"(a[3]), "r"(b0), "r"(b1));
}
__device__ __forceinline__ float pv(float2 bb, float Ai, float A2i, float thr,
                                    unsigned mk) {
    float v = (bb.x > thr) ? Ai * bb.x : A2i * bb.y;
    return mk ? v : 0.f;
}
__device__ __forceinline__ void pack_split(float p0, float p1, uint32_t& hi,
                                           uint32_t& lo) {
    __nv_bfloat162 h = __floats2bfloat162_rn(p0, p1);
    hi = *(uint32_t*)&h;
    float h0 = __uint_as_float(hi << 16);
    float h1 = __uint_as_float(hi & 0xFFFF0000u);
    __nv_bfloat162 l = __floats2bfloat162_rn(p0 - h0, p1 - h1);
    lo = *(uint32_t*)&l;
}

// ---------------- f32x2 helpers (kA GEMM) ----------------
__device__ __forceinline__ unsigned long long pk2(float lo, float hi) {
    unsigned long long r;
    asm("mov.b64 %0, {%1, %2};" : "=l"(r) : "f"(lo), "f"(hi));
    return r;
}
__device__ __forceinline__ void upk2(unsigned long long v, float& lo, float& hi) {
    asm("mov.b64 {%0, %1}, %2;" : "=f"(lo), "=f"(hi) : "l"(v));
}
__device__ __forceinline__ void fma2(unsigned long long& d, unsigned long long a,
                                     unsigned long long b) {
    asm("fma.rn.f32x2 %0, %1, %2, %0;" : "+l"(d) : "l"(a), "l"(b));
}

// ============================================================
// Kernel A: h = x @ W ; e_s, e_d ; hi/lo bf16 split of h^T via smem transpose
// ============================================================
__global__ __launch_bounds__(128) void kA(const float* __restrict__ x,
                                          const float* __restrict__ W,
                                          const float* __restrict__ asrc,
                                          const float* __restrict__ adst) {
    __shared__ __align__(16) float ws[F * C];                  // 32 KB
    __shared__ __align__(16) __nv_bfloat16 s_hi[C * 32];       // 4 KB
    __shared__ __align__(16) __nv_bfloat16 s_lo[C * 32];       // 4 KB
    int tid = threadIdx.x;
    int t = blockIdx.y;
    int n0 = blockIdx.x * 32;

    const float4* wg = (const float4*)W;
    float4* ws4 = (float4*)ws;
#pragma unroll
    for (int r = 0; r < 16; r++) ws4[tid + r * 128] = wg[tid + r * 128];
    __syncthreads();

    int row = tid >> 2;
    int cg = (tid & 3) * 16;
    int n = n0 + row;
    const float* xrow = x + ((size_t)t * N + n) * F;

    unsigned long long acc2[8];
#pragma unroll
    for (int q = 0; q < 8; q++) acc2[q] = 0ull;

#pragma unroll 4
    for (int k = 0; k < F; k += 4) {
        float4 xq = *(const float4*)(xrow + k);
        float xv[4] = {xq.x, xq.y, xq.z, xq.w};
#pragma unroll
        for (int s = 0; s < 4; s++) {
            unsigned long long pp = pk2(xv[s], xv[s]);
            const ulonglong2* wr = (const ulonglong2*)(ws + (k + s) * C + cg);
#pragma unroll
            for (int q = 0; q < 4; q++) {
                ulonglong2 wv = wr[q];
                fma2(acc2[2 * q], wv.x, pp);
                fma2(acc2[2 * q + 1], wv.y, pp);
            }
        }
    }

    float hc[16];
#pragma unroll
    for (int q = 0; q < 8; q++) upk2(acc2[q], hc[2 * q], hc[2 * q + 1]);

    // split + transpose into smem
#pragma unroll
    for (int c = 0; c < 16; c++) {
        __nv_bfloat16 hb = __float2bfloat16_rn(hc[c]);
        float rem = hc[c] - __bfloat162float(hb);
        s_hi[(cg + c) * 32 + row] = hb;
        s_lo[(cg + c) * 32 + row] = __float2bfloat16_rn(rem);
    }

    float es = 0.f, ed = 0.f;
#pragma unroll
    for (int c = 0; c < 16; c++) {
        es = fmaf(hc[c], asrc[cg + c], es);
        ed = fmaf(hc[c], adst[cg + c], ed);
    }
    es += __shfl_down_sync(0xffffffffu, es, 1, 4);
    es += __shfl_down_sync(0xffffffffu, es, 2, 4);
    ed += __shfl_down_sync(0xffffffffu, ed, 1, 4);
    ed += __shfl_down_sync(0xffffffffu, ed, 2, 4);
    if ((tid & 3) == 0) {
        g_es[t * N + n] = es;
        g_ed[t * N + n] = ed;
    }
    __syncthreads();

    // coalesced-ish writeout: 256 uint4 units per array; unit u: c=u>>2, seg=u&3
    __nv_bfloat16* dhi = g_hThi + (size_t)t * C * N;
    __nv_bfloat16* dlo = g_hTlo + (size_t)t * C * N;
#pragma unroll
    for (int r = 0; r < 2; r++) {
        int u = tid + r * 128;
        int c = u >> 2, seg = u & 3;
        *(uint4*)(dhi + (size_t)c * N + n0 + seg * 8) = ((const uint4*)s_hi)[u];
        *(uint4*)(dlo + (size_t)c * N + n0 + seg * 8) = ((const uint4*)s_lo)[u];
    }
}

// ============================================================
// Kernel B: masked-softmax aggregation via split-bf16 HMMA
// CTA = 128 i-rows x full K, 8 warps x 16 rows, 32 chunks of 64 j.
// ============================================================
#define BB_OFF   0         // 2048 float2 = 16384
#define HS_OFF   16384     // 2 bufs x (hi,lo) x 64*72 bf16 = 4*9216 = 36864
#define ADJ_OFF  53248     // 64*128 ints = 32768
#define MSB_OFF  86016     // 256 words = 1024
#define RED_OFF  87040     // 256 f32 = 1024
#define BIAS_OFF 88064     // 64 f32 = 256
#define KB_SMEM  88320

__global__ __launch_bounds__(256) void kB(const int* __restrict__ adj,
                                          const float* __restrict__ bias) {
    extern __shared__ __align__(16) char sm[];
    float2* BB = (float2*)(sm + BB_OFF);
    int* adjraw = (int*)(sm + ADJ_OFF);
    unsigned* msb = (unsigned*)(sm + MSB_OFF);
    float* red = (float*)(sm + RED_OFF);
    float* bias_s = (float*)(sm + BIAS_OFF);
    uint32_t smb = smem_u32(sm);

    int tid = threadIdx.x;
    int wid = tid >> 5;
    int lane = tid & 31;
    int t = blockIdx.y;
    int i0 = blockIdx.x * 128;

    const int* abase = adj + (size_t)t * N * N + i0;
    const __nv_bfloat16* hhib = g_hThi + (size_t)t * C * N;
    const __nv_bfloat16* hlob = g_hTlo + (size_t)t * C * N;

    // ---- prologue: start chunk-0 loads immediately ----
    {
#pragma unroll
        for (int r = 0; r < 8; r++) {
            int u = tid + r * 256;
            int j = u >> 5, off = u & 31;
            CP_ASYNC16(smb + ADJ_OFF + u * 16, abase + (size_t)j * N + off * 4);
        }
#pragma unroll
        for (int r = 0; r < 2; r++) {
            int u = tid + r * 256;
            int c = u >> 3, o = u & 7;
            uint32_t doff = (uint32_t)(c * 72 + o * 8) * 2;
            CP_ASYNC16(smb + HS_OFF + doff, hhib + (size_t)c * N + o * 8);
            CP_ASYNC16(smb + HS_OFF + 9216 + doff, hlob + (size_t)c * N + o * 8);
        }
        CP_COMMIT();
    }

    if (tid < 16) ((float4*)bias_s)[tid] = ((const float4*)bias)[tid];

    // ---- e_s staging + max + transform ----
    float lmax = -1e30f;
#pragma unroll
    for (int r = 0; r < 8; r++) {
        float v = g_es[t * N + tid + r * 256];
        BB[tid + r * 256].x = v;
        lmax = fmaxf(lmax, v);
    }
    red[tid] = lmax;
    __syncthreads();
    for (int s = 128; s > 0; s >>= 1) {
        if (tid < s) red[tid] = fmaxf(red[tid], red[tid + s]);
        __syncthreads();
    }
    float esmax = red[0];
#pragma unroll
    for (int r = 0; r < 8; r++) {
        int j = tid + r * 256;
        float v = BB[j].x;  // written by this same thread above
        BB[j] = make_float2(__expf(v - esmax), __expf(0.2f * (v - esmax)));
    }

    // ---- per-row constants ----
    int il1 = wid * 16 + (lane >> 2);
    int il2 = il1 + 8;
    int gi1 = i0 + il1, gi2 = i0 + il2;
    float ed1 = g_ed[t * N + gi1], ed2 = g_ed[t * N + gi2];
    float xm1 = ed1 + esmax, xm2 = ed2 + esmax;
    float M1 = fmaxf(xm1, 0.2f * xm1), M2 = fmaxf(xm2, 0.2f * xm2);
    float Ai1 = __expf(xm1 - M1), A2i1 = __expf(0.2f * xm1 - M1), thr1 = __expf(-xm1);
    float Ai2 = __expf(xm2 - M2), A2i2 = __expf(0.2f * xm2 - M2), thr2 = __expf(-xm2);
    int igq = il1 >> 5;          // same 32-group for il1 and il2
    int b1 = il1 & 31, b2 = b1 + 8;

    float d[8][4];
#pragma unroll
    for (int nt = 0; nt < 8; nt++)
#pragma unroll
        for (int q = 0; q < 4; q++) d[nt][q] = 0.f;
    float sum1 = 0.f, sum2 = 0.f;

    int q = lane & 3;
    int c0j = 2 * q;
    uint32_t rowa = ((lane >> 4) << 3) + (lane & 7);
    uint32_t cola = ((lane >> 3) & 1) * 8;

    __syncthreads();   // BB ready

    int buf = 0;
#pragma unroll 1
    for (int k = 0; k < 32; k++) {
        int j0 = k * 64;
        CP_WAIT0();
        __syncthreads();   // chunk-k data landed; prior compute done

        // ---- ballot phase: adjraw -> bit masks (self-loop folded in) ----
#pragma unroll 4
        for (int it = 0; it < 32; it++) {
            int pr = wid * 32 + it;
            int j = pr >> 2, ig = pr & 3;
            int v = adjraw[j * 128 + ig * 32 + lane];
            unsigned bm = __ballot_sync(0xffffffffu,
                                        (v != 0) || (j0 + j == i0 + ig * 32 + lane));
            if (lane == 0) msb[j * 4 + ig] = bm;
        }
        __syncthreads();   // msb ready, adjraw consumed

        // ---- prefetch chunk k+1 ----
        if (k + 1 < 32) {
            int jn = j0 + 64;
            int nb = buf ^ 1;
#pragma unroll
            for (int r = 0; r < 8; r++) {
                int u = tid + r * 256;
                int j = u >> 5, off = u & 31;
                CP_ASYNC16(smb + ADJ_OFF + u * 16,
                           abase + (size_t)(jn + j) * N + off * 4);
            }
#pragma unroll
            for (int r = 0; r < 2; r++) {
                int u = tid + r * 256;
                int c = u >> 3, o = u & 7;
                uint32_t doff = (uint32_t)(c * 72 + o * 8) * 2;
                uint32_t hb = smb + HS_OFF + (uint32_t)(nb * 2) * 9216;
                CP_ASYNC16(hb + doff, hhib + (size_t)c * N + jn + o * 8);
                CP_ASYNC16(hb + 9216 + doff, hlob + (size_t)c * N + jn + o * 8);
            }
        }
        CP_COMMIT();

        // ---- compute chunk k ----
        uint32_t hhi_u = smb + HS_OFF + (uint32_t)(buf * 2) * 9216;
        uint32_t hlo_u = hhi_u + 9216;

#pragma unroll
        for (int kt = 0; kt < 4; kt++) {
            int jb = j0 + kt * 16 + c0j;
            float2 bA = BB[jb], bBv = BB[jb + 1], bCv = BB[jb + 8], bDv = BB[jb + 9];
            int jl = kt * 16 + c0j;
            unsigned mA = msb[jl * 4 + igq];
            unsigned mB = msb[(jl + 1) * 4 + igq];
            unsigned mC = msb[(jl + 8) * 4 + igq];
            unsigned mD = msb[(jl + 9) * 4 + igq];

            float p10 = pv(bA, Ai1, A2i1, thr1, (mA >> b1) & 1u);
            float p11 = pv(bBv, Ai1, A2i1, thr1, (mB >> b1) & 1u);
            float p18 = pv(bCv, Ai1, A2i1, thr1, (mC >> b1) & 1u);
            float p19 = pv(bDv, Ai1, A2i1, thr1, (mD >> b1) & 1u);
            float p20 = pv(bA, Ai2, A2i2, thr2, (mA >> b2) & 1u);
            float p21 = pv(bBv, Ai2, A2i2, thr2, (mB >> b2) & 1u);
            float p28 = pv(bCv, Ai2, A2i2, thr2, (mC >> b2) & 1u);
            float p29 = pv(bDv, Ai2, A2i2, thr2, (mD >> b2) & 1u);
            sum1 += (p10 + p11) + (p18 + p19);
            sum2 += (p20 + p21) + (p28 + p29);

            uint32_t ahi[4], alo[4];
            pack_split(p10, p11, ahi[0], alo[0]);
            pack_split(p20, p21, ahi[1], alo[1]);
            pack_split(p18, p19, ahi[2], alo[2]);
            pack_split(p28, p29, ahi[3], alo[3]);

            uint32_t lcol = (uint32_t)(kt * 16) + cola;
#pragma unroll
            for (int cg = 0; cg < 4; cg++) {
                uint32_t roff = ((uint32_t)(cg * 16) + rowa) * 72 * 2 + lcol * 2;
                uint32_t h0, h1, h2, h3, l0, l1, l2, l3;
                ldsm4(h0, h1, h2, h3, hhi_u + roff);
                ldsm4(l0, l1, l2, l3, hlo_u + roff);
                mma16816(d[cg * 2], ahi, h0, h1);
                mma16816(d[cg * 2], ahi, l0, l1);
                mma16816(d[cg * 2], alo, h0, h1);
                mma16816(d[cg * 2 + 1], ahi, h2, h3);
                mma16816(d[cg * 2 + 1], ahi, l2, l3);
                mma16816(d[cg * 2 + 1], alo, h2, h3);
            }
        }
        buf ^= 1;
    }

    // ---- row-sum reduce within quad + epilogue ----
    sum1 += __shfl_xor_sync(0xffffffffu, sum1, 1);
    sum1 += __shfl_xor_sync(0xffffffffu, sum1, 2);
    sum2 += __shfl_xor_sync(0xffffffffu, sum2, 1);
    sum2 += __shfl_xor_sync(0xffffffffu, sum2, 2);
    float s1 = 1.f / sum1, s2 = 1.f / sum2;

    float* o1 = g_out + ((size_t)t * N + gi1) * C;
    float* o2 = g_out + ((size_t)t * N + gi2) * C;
    int q2 = 2 * q;
#pragma unroll
    for (int nt = 0; nt < 8; nt++) {
        int c = nt * 8 + q2;
        float2 v1 = make_float2(d[nt][0] * s1 + bias_s[c], d[nt][1] * s1 + bias_s[c + 1]);
        float2 v2 = make_float2(d[nt][2] * s2 + bias_s[c], d[nt][3] * s2 + bias_s[c + 1]);
        *(float2*)(o1 + c) = v1;
        *(float2*)(o2 + c) = v2;
    }
}

// ============================================================
// Kernel C1: tem[t,n] = cos_sim(out[t,n], out[t+1,n])
// ============================================================
__global__ __launch_bounds__(256) void kC1() {
    int w = (blockIdx.x * 256 + threadIdx.x) >> 5;
    int lane = threadIdx.x & 31;
    if (w >= (T - 1) * N) return;
    int t = w / N, n = w % N;
    const float2* A = (const float2*)(g_out + ((size_t)t * N + n) * C);
    const float2* B = (const float2*)(g_out + ((size_t)(t + 1) * N + n) * C);
    float2 a = A[lane], b = B[lane];
    float dot = a.x * b.x + a.y * b.y;
    float na = a.x * a.x + a.y * a.y;
    float nb = b.x * b.x + b.y * b.y;
#pragma unroll
    for (int off = 16; off > 0; off >>= 1) {
        dot += __shfl_xor_sync(0xffffffffu, dot, off);
        na += __shfl_xor_sync(0xffffffffu, na, off);
        nb += __shfl_xor_sync(0xffffffffu, nb, off);
    }
    if (lane == 0) {
        float d1 = fmaxf(sqrtf(na), 1e-8f);
        float d2 = fmaxf(sqrtf(nb), 1e-8f);
        g_tem[w] = dot / (d1 * d2);
    }
}

// ============================================================
// Kernel C2: final = out + [t>=1](tem[t-1]*out[t-1])@t2w + [t<7](tem[t]*out[t+1])@t1w
// ============================================================
__global__ __launch_bounds__(256) void kC2(const float* __restrict__ t1w,
                                           const float* __restrict__ t2w,
                                           float* __restrict__ out) {
    __shared__ __align__(16) float w1[C * C];
    __shared__ __align__(16) float w2[C * C];
    int tid = threadIdx.x;
    int t = blockIdx.y;
    int n0 = blockIdx.x * 32;
#pragma unroll
    for (int r = 0; r < 4; r++) {
        ((float4*)w1)[tid + r * 256] = ((const float4*)t1w)[tid + r * 256];
        ((float4*)w2)[tid + r * 256] = ((const float4*)t2w)[tid + r * 256];
    }
    __syncthreads();

    int nl = tid >> 3;
    int dg = (tid & 7) * 8;
    int n = n0 + nl;
    size_t rowo = ((size_t)t * N + n) * C;

    float r[8];
#pragma unroll
    for (int qq = 0; qq < 2; qq++) {
        float4 v = *(const float4*)(g_out + rowo + dg + qq * 4);
        r[qq * 4] = v.x;
        r[qq * 4 + 1] = v.y;
        r[qq * 4 + 2] = v.z;
        r[qq * 4 + 3] = v.w;
    }

    if (t < T - 1) {
        float tm = g_tem[t * N + n];
        const float* bro = g_out + ((size_t)(t + 1) * N + n) * C;
        for (int c = 0; c < C; c += 4) {
            float4 bv = *(const float4*)(bro + c);
            float u[4] = {tm * bv.x, tm * bv.y, tm * bv.z, tm * bv.w};
#pragma unroll
            for (int s = 0; s < 4; s++) {
                const float* wr = w1 + (c + s) * C + dg;
#pragma unroll
                for (int dd = 0; dd < 8; dd++) r[dd] = fmaf(u[s], wr[dd], r[dd]);
            }
        }
    }
    if (t >= 1) {
        float tm = g_tem[(t - 1) * N + n];
        const float* aro = g_out + ((size_t)(t - 1) * N + n) * C;
        for (int c = 0; c < C; c += 4) {
            float4 av = *(const float4*)(aro + c);
            float u[4] = {tm * av.x, tm * av.y, tm * av.z, tm * av.w};
#pragma unroll
            for (int s = 0; s < 4; s++) {
                const float* wr = w2 + (c + s) * C + dg;
#pragma unroll
                for (int dd = 0; dd < 8; dd++) r[dd] = fmaf(u[s], wr[dd], r[dd]);
            }
        }
    }

#pragma unroll
    for (int qq = 0; qq < 2; qq++) {
        *(float4*)(out + rowo + dg + qq * 4) =
            make_float4(r[qq * 4], r[qq * 4 + 1], r[qq * 4 + 2], r[qq * 4 + 3]);
    }
}

// ============================================================
extern "C" void kernel_launch(void* const* d_in, const int* in_sizes, int n_in,
                              void* d_out, int out_size) {
    const float* x = (const float*)d_in[0];
    const int* adj = (const int*)d_in[1];
    const float* W = (const float*)d_in[2];
    const float* asrc = (const float*)d_in[3];
    const float* adst = (const float*)d_in[4];
    const float* bias = (const float*)d_in[5];
    const float* t1w = (const float*)d_in[6];
    const float* t2w = (const float*)d_in[7];
    float* out = (float*)d_out;

    cudaFuncSetAttribute(kB, cudaFuncAttributeMaxDynamicSharedMemorySize, KB_SMEM);

    kA<<<dim3(N / 32, T), 128>>>(x, W, asrc, adst);
    kB<<<dim3(N / 128, T), 256, KB_SMEM>>>(adj, bias);
    kC1<<<((T - 1) * N * 32 + 255) / 256, 256>>>();
    kC2<<<dim3(N / 32, T), 256>>>(t1w, t2w, out);
}

// round 5
// speedup vs baseline: 1.8602x; 1.1261x over previous
#include <cuda_runtime.h>
#include <cuda_fp16.h>
#include <math.h>
#include <stdint.h>

#define T 8
#define N 2048
#define F 128
#define C 64

// ---------------- device scratch ----------------
__device__ float g_es[T * N];
__device__ float g_ed[T * N];
__device__ float g_out[T * N * C];
__device__ __half g_hThi[T * C * N];   // h transposed hi fp16: [t][c][n]
__device__ __half g_hTlo[T * C * N];   // residual lo fp16

// ---------------- helpers ----------------
__device__ __forceinline__ uint32_t smem_u32(const void* p) {
    uint32_t a;
    asm("{ .reg .u64 t; cvta.to.shared.u64 t, %1; cvt.u32.u64 %0, t; }"
        : "=r"(a) : "l"(p));
    return a;
}
#define CP_ASYNC16(dst, src) \
    asm volatile("cp.async.cg.shared.global [%0], [%1], 16;" :: "r"(dst), "l"(src) : "memory")
#define CP_COMMIT() asm volatile("cp.async.commit_group;" ::: "memory")
#define CP_WAIT0() asm volatile("cp.async.wait_group 0;" ::: "memory")

__device__ __forceinline__ void ldsm4(uint32_t& r0, uint32_t& r1, uint32_t& r2,
                                      uint32_t& r3, uint32_t addr) {
    asm volatile("ldmatrix.sync.aligned.m8n8.x4.shared.b16 {%0,%1,%2,%3}, [%4];"
                 : "=r"(r0), "=r"(r1), "=r"(r2), "=r"(r3) : "r"(addr));
}
__device__ __forceinline__ void mma16816(float* d, const uint32_t* a, uint32_t b0,
                                         uint32_t b1) {
    asm volatile(
        "mma.sync.aligned.m16n8k16.row.col.f32.f16.f16.f32 "
        "{%0,%1,%2,%3}, {%4,%5,%6,%7}, {%8,%9}, {%0,%1,%2,%3};"
        : "+f"(d[0]), "+f"(d[1]), "+f"(d[2]), "+f"(d[3])
        : "r"(a[0]), "r"(a[1]), "r"(a[2]), "r"(a[3]), "r"(b0), "r"(b1));
}
__device__ __forceinline__ float pv(float2 bb, float Ai, float A2i, float thr,
                                    unsigned mk) {
    float v = (bb.x > thr) ? Ai * bb.x : A2i * bb.y;
    return mk ? v : 0.f;
}
__device__ __forceinline__ uint32_t pack_p(float p0, float p1) {
    __half2 h = __floats2half2_rn(p0, p1);
    return *(uint32_t*)&h;
}

// ---------------- f32x2 helpers ----------------
__device__ __forceinline__ unsigned long long pk2(float lo, float hi) {
    unsigned long long r;
    asm("mov.b64 %0, {%1, %2};" : "=l"(r) : "f"(lo), "f"(hi));
    return r;
}
__device__ __forceinline__ void upk2(unsigned long long v, float& lo, float& hi) {
    asm("mov.b64 {%0, %1}, %2;" : "=f"(lo), "=f"(hi) : "l"(v));
}
__device__ __forceinline__ void fma2(unsigned long long& d, unsigned long long a,
                                     unsigned long long b) {
    asm("fma.rn.f32x2 %0, %1, %2, %0;" : "+l"(d) : "l"(a), "l"(b));
}

// ============================================================
// Kernel A: h = x @ W ; e_s, e_d ; hi/lo fp16 split of h^T.
// 2 rows per thread (shared weight reads). Block=128 -> 64 rows.
// ============================================================
__global__ __launch_bounds__(128) void kA(const float* __restrict__ x,
                                          const float* __restrict__ W,
                                          const float* __restrict__ asrc,
                                          const float* __restrict__ adst) {
    __shared__ __align__(16) float ws[F * C];         // 32 KB
    __shared__ __align__(16) __half s_hi[C * 64];     // 8 KB
    __shared__ __align__(16) __half s_lo[C * 64];     // 8 KB
    int tid = threadIdx.x;
    int t = blockIdx.y;
    int n0 = blockIdx.x * 64;

    const float4* wg = (const float4*)W;
    float4* ws4 = (float4*)ws;
#pragma unroll
    for (int r = 0; r < 16; r++) ws4[tid + r * 128] = wg[tid + r * 128];
    __syncthreads();

    int row = tid >> 2;
    int cg = (tid & 3) * 16;
    int na = n0 + row, nb = n0 + row + 32;
    const float* xa = x + ((size_t)t * N + na) * F;
    const float* xb = x + ((size_t)t * N + nb) * F;

    unsigned long long acca[8], accb[8];
#pragma unroll
    for (int q = 0; q < 8; q++) { acca[q] = 0ull; accb[q] = 0ull; }

#pragma unroll 4
    for (int k = 0; k < F; k += 4) {
        float4 qa = *(const float4*)(xa + k);
        float4 qb = *(const float4*)(xb + k);
        float va[4] = {qa.x, qa.y, qa.z, qa.w};
        float vb[4] = {qb.x, qb.y, qb.z, qb.w};
#pragma unroll
        for (int s = 0; s < 4; s++) {
            unsigned long long pa = pk2(va[s], va[s]);
            unsigned long long pb = pk2(vb[s], vb[s]);
            const ulonglong2* wr = (const ulonglong2*)(ws + (k + s) * C + cg);
#pragma unroll
            for (int q = 0; q < 4; q++) {
                ulonglong2 wv = wr[q];
                fma2(acca[2 * q], wv.x, pa);
                fma2(acca[2 * q + 1], wv.y, pa);
                fma2(accb[2 * q], wv.x, pb);
                fma2(accb[2 * q + 1], wv.y, pb);
            }
        }
    }

    float ha[16], hb[16];
#pragma unroll
    for (int q = 0; q < 8; q++) {
        upk2(acca[q], ha[2 * q], ha[2 * q + 1]);
        upk2(accb[q], hb[2 * q], hb[2 * q + 1]);
    }

    // split + transpose into smem
#pragma unroll
    for (int c = 0; c < 16; c++) {
        __half h1 = __float2half_rn(ha[c]);
        __half h2 = __float2half_rn(hb[c]);
        s_hi[(cg + c) * 64 + row] = h1;
        s_hi[(cg + c) * 64 + row + 32] = h2;
        s_lo[(cg + c) * 64 + row] = __float2half_rn(ha[c] - __half2float(h1));
        s_lo[(cg + c) * 64 + row + 32] = __float2half_rn(hb[c] - __half2float(h2));
    }

    float esa = 0.f, eda = 0.f, esb = 0.f, edb = 0.f;
#pragma unroll
    for (int c = 0; c < 16; c++) {
        float as = asrc[cg + c], ad = adst[cg + c];
        esa = fmaf(ha[c], as, esa);
        eda = fmaf(ha[c], ad, eda);
        esb = fmaf(hb[c], as, esb);
        edb = fmaf(hb[c], ad, edb);
    }
    esa += __shfl_down_sync(0xffffffffu, esa, 1, 4);
    esa += __shfl_down_sync(0xffffffffu, esa, 2, 4);
    eda += __shfl_down_sync(0xffffffffu, eda, 1, 4);
    eda += __shfl_down_sync(0xffffffffu, eda, 2, 4);
    esb += __shfl_down_sync(0xffffffffu, esb, 1, 4);
    esb += __shfl_down_sync(0xffffffffu, esb, 2, 4);
    edb += __shfl_down_sync(0xffffffffu, edb, 1, 4);
    edb += __shfl_down_sync(0xffffffffu, edb, 2, 4);
    if ((tid & 3) == 0) {
        g_es[t * N + na] = esa;
        g_ed[t * N + na] = eda;
        g_es[t * N + nb] = esb;
        g_ed[t * N + nb] = edb;
    }
    __syncthreads();

    // writeout: 512 uint4 units per array; u: c=u>>3, seg=u&7
    __half* dhi = g_hThi + (size_t)t * C * N;
    __half* dlo = g_hTlo + (size_t)t * C * N;
#pragma unroll
    for (int r = 0; r < 4; r++) {
        int u = tid + r * 128;
        int c = u >> 3, seg = u & 7;
        *(uint4*)(dhi + (size_t)c * N + n0 + seg * 8) = ((const uint4*)s_hi)[u];
        *(uint4*)(dlo + (size_t)c * N + n0 + seg * 8) = ((const uint4*)s_lo)[u];
    }
}

// ============================================================
// Kernel B: masked-softmax aggregation via fp16 HMMA (P-hi x H-hi + P-hi x H-lo)
// CTA = 128 i-rows x full K, 8 warps x 16 rows, 32 chunks of 64 j.
// ============================================================
#define BB_OFF   0         // 2048 float2 = 16384
#define HS_OFF   16384     // 2 bufs x (hi,lo) x 64*72 fp16 = 4*9216 = 36864
#define ADJ_OFF  53248     // 64*128 ints = 32768
#define MSB_OFF  86016     // 256 words = 1024
#define RED_OFF  87040     // 256 f32 = 1024
#define BIAS_OFF 88064     // 64 f32 = 256
#define KB_SMEM  88320

__global__ __launch_bounds__(256) void kB(const int* __restrict__ adj,
                                          const float* __restrict__ bias) {
    extern __shared__ __align__(16) char sm[];
    float2* BB = (float2*)(sm + BB_OFF);
    int* adjraw = (int*)(sm + ADJ_OFF);
    unsigned* msb = (unsigned*)(sm + MSB_OFF);
    float* red = (float*)(sm + RED_OFF);
    float* bias_s = (float*)(sm + BIAS_OFF);
    uint32_t smb = smem_u32(sm);

    int tid = threadIdx.x;
    int wid = tid >> 5;
    int lane = tid & 31;
    int t = blockIdx.y;
    int i0 = blockIdx.x * 128;

    const int* abase = adj + (size_t)t * N * N + i0;
    const __half* hhib = g_hThi + (size_t)t * C * N;
    const __half* hlob = g_hTlo + (size_t)t * C * N;

    // ---- prologue: chunk-0 loads ----
    {
#pragma unroll
        for (int r = 0; r < 8; r++) {
            int u = tid + r * 256;
            int j = u >> 5, off = u & 31;
            CP_ASYNC16(smb + ADJ_OFF + u * 16, abase + (size_t)j * N + off * 4);
        }
#pragma unroll
        for (int r = 0; r < 2; r++) {
            int u = tid + r * 256;
            int c = u >> 3, o = u & 7;
            uint32_t doff = (uint32_t)(c * 72 + o * 8) * 2;
            CP_ASYNC16(smb + HS_OFF + doff, hhib + (size_t)c * N + o * 8);
            CP_ASYNC16(smb + HS_OFF + 9216 + doff, hlob + (size_t)c * N + o * 8);
        }
        CP_COMMIT();
    }

    if (tid < 16) ((float4*)bias_s)[tid] = ((const float4*)bias)[tid];

    // ---- e_s staging + max + transform ----
    float lmax = -1e30f;
#pragma unroll
    for (int r = 0; r < 8; r++) {
        float v = g_es[t * N + tid + r * 256];
        BB[tid + r * 256].x = v;
        lmax = fmaxf(lmax, v);
    }
    red[tid] = lmax;
    __syncthreads();
    for (int s = 128; s > 0; s >>= 1) {
        if (tid < s) red[tid] = fmaxf(red[tid], red[tid + s]);
        __syncthreads();
    }
    float esmax = red[0];
#pragma unroll
    for (int r = 0; r < 8; r++) {
        int j = tid + r * 256;
        float v = BB[j].x;
        BB[j] = make_float2(__expf(v - esmax), __expf(0.2f * (v - esmax)));
    }

    // ---- per-row constants ----
    int il1 = wid * 16 + (lane >> 2);
    int il2 = il1 + 8;
    int gi1 = i0 + il1, gi2 = i0 + il2;
    float ed1 = g_ed[t * N + gi1], ed2 = g_ed[t * N + gi2];
    float xm1 = ed1 + esmax, xm2 = ed2 + esmax;
    float M1 = fmaxf(xm1, 0.2f * xm1), M2 = fmaxf(xm2, 0.2f * xm2);
    float Ai1 = __expf(xm1 - M1), A2i1 = __expf(0.2f * xm1 - M1), thr1 = __expf(-xm1);
    float Ai2 = __expf(xm2 - M2), A2i2 = __expf(0.2f * xm2 - M2), thr2 = __expf(-xm2);
    int igq = il1 >> 5;
    int b1 = il1 & 31, b2 = b1 + 8;

    float d[8][4];
#pragma unroll
    for (int nt = 0; nt < 8; nt++)
#pragma unroll
        for (int q = 0; q < 4; q++) d[nt][q] = 0.f;
    float sum1 = 0.f, sum2 = 0.f;

    int q = lane & 3;
    int c0j = 2 * q;
    uint32_t rowa = ((lane >> 4) << 3) + (lane & 7);
    uint32_t cola = ((lane >> 3) & 1) * 8;

    __syncthreads();   // BB ready

    int buf = 0;
#pragma unroll 1
    for (int k = 0; k < 32; k++) {
        int j0 = k * 64;
        CP_WAIT0();
        __syncthreads();

        // ---- ballot: adjraw -> bit masks (self-loop folded) ----
#pragma unroll 4
        for (int it = 0; it < 32; it++) {
            int pr = wid * 32 + it;
            int j = pr >> 2, ig = pr & 3;
            int v = adjraw[j * 128 + ig * 32 + lane];
            unsigned bm = __ballot_sync(0xffffffffu,
                                        (v != 0) || (j0 + j == i0 + ig * 32 + lane));
            if (lane == 0) msb[j * 4 + ig] = bm;
        }
        __syncthreads();

        // ---- prefetch chunk k+1 ----
        if (k + 1 < 32) {
            int jn = j0 + 64;
            int nb = buf ^ 1;
#pragma unroll
            for (int r = 0; r < 8; r++) {
                int u = tid + r * 256;
                int j = u >> 5, off = u & 31;
                CP_ASYNC16(smb + ADJ_OFF + u * 16,
                           abase + (size_t)(jn + j) * N + off * 4);
            }
#pragma unroll
            for (int r = 0; r < 2; r++) {
                int u = tid + r * 256;
                int c = u >> 3, o = u & 7;
                uint32_t doff = (uint32_t)(c * 72 + o * 8) * 2;
                uint32_t hb = smb + HS_OFF + (uint32_t)(nb * 2) * 9216;
                CP_ASYNC16(hb + doff, hhib + (size_t)c * N + jn + o * 8);
                CP_ASYNC16(hb + 9216 + doff, hlob + (size_t)c * N + jn + o * 8);
            }
        }
        CP_COMMIT();

        // ---- compute chunk k ----
        uint32_t hhi_u = smb + HS_OFF + (uint32_t)(buf * 2) * 9216;
        uint32_t hlo_u = hhi_u + 9216;

#pragma unroll
        for (int kt = 0; kt < 4; kt++) {
            int jb = j0 + kt * 16 + c0j;
            float2 bA = BB[jb], bBv = BB[jb + 1], bCv = BB[jb + 8], bDv = BB[jb + 9];
            int jl = kt * 16 + c0j;
            unsigned mA = msb[jl * 4 + igq];
            unsigned mB = msb[(jl + 1) * 4 + igq];
            unsigned mC = msb[(jl + 8) * 4 + igq];
            unsigned mD = msb[(jl + 9) * 4 + igq];

            float p10 = pv(bA, Ai1, A2i1, thr1, (mA >> b1) & 1u);
            float p11 = pv(bBv, Ai1, A2i1, thr1, (mB >> b1) & 1u);
            float p18 = pv(bCv, Ai1, A2i1, thr1, (mC >> b1) & 1u);
            float p19 = pv(bDv, Ai1, A2i1, thr1, (mD >> b1) & 1u);
            float p20 = pv(bA, Ai2, A2i2, thr2, (mA >> b2) & 1u);
            float p21 = pv(bBv, Ai2, A2i2, thr2, (mB >> b2) & 1u);
            float p28 = pv(bCv, Ai2, A2i2, thr2, (mC >> b2) & 1u);
            float p29 = pv(bDv, Ai2, A2i2, thr2, (mD >> b2) & 1u);
            sum1 += (p10 + p11) + (p18 + p19);
            sum2 += (p20 + p21) + (p28 + p29);

            uint32_t ap[4];
            ap[0] = pack_p(p10, p11);
            ap[1] = pack_p(p20, p21);
            ap[2] = pack_p(p18, p19);
            ap[3] = pack_p(p28, p29);

            uint32_t lcol = (uint32_t)(kt * 16) + cola;
#pragma unroll
            for (int cg = 0; cg < 4; cg++) {
                uint32_t roff = ((uint32_t)(cg * 16) + rowa) * 72 * 2 + lcol * 2;
                uint32_t h0, h1, h2, h3, l0, l1, l2, l3;
                ldsm4(h0, h1, h2, h3, hhi_u + roff);
                ldsm4(l0, l1, l2, l3, hlo_u + roff);
                mma16816(d[cg * 2], ap, h0, h1);
                mma16816(d[cg * 2], ap, l0, l1);
                mma16816(d[cg * 2 + 1], ap, h2, h3);
                mma16816(d[cg * 2 + 1], ap, l2, l3);
            }
        }
        buf ^= 1;
    }

    // ---- reduce + epilogue ----
    sum1 += __shfl_xor_sync(0xffffffffu, sum1, 1);
    sum1 += __shfl_xor_sync(0xffffffffu, sum1, 2);
    sum2 += __shfl_xor_sync(0xffffffffu, sum2, 1);
    sum2 += __shfl_xor_sync(0xffffffffu, sum2, 2);
    float s1 = 1.f / sum1, s2 = 1.f / sum2;

    float* o1 = g_out + ((size_t)t * N + gi1) * C;
    float* o2 = g_out + ((size_t)t * N + gi2) * C;
    int q2 = 2 * q;
#pragma unroll
    for (int nt = 0; nt < 8; nt++) {
        int c = nt * 8 + q2;
        *(float2*)(o1 + c) =
            make_float2(d[nt][0] * s1 + bias_s[c], d[nt][1] * s1 + bias_s[c + 1]);
        *(float2*)(o2 + c) =
            make_float2(d[nt][2] * s2 + bias_s[c], d[nt][3] * s2 + bias_s[c + 1]);
    }
}

// ============================================================
// Kernel C (merged): inline cosine sims + temporal matvecs.
// Block 256 = 32 nodes x 8 dim-groups. final = cur + tem_prev*(prev@t2w)
//                                            + tem_next*(next@t1w)
// ============================================================
__global__ __launch_bounds__(256) void kC(const float* __restrict__ t1w,
                                          const float* __restrict__ t2w,
                                          float* __restrict__ out) {
    __shared__ __align__(16) float w1[C * C];     // 16 KB
    __shared__ __align__(16) float w2[C * C];     // 16 KB
    __shared__ __align__(16) float2 us[32 * C];   // 16 KB  (u1=next-term, u2=prev-term)
    int tid = threadIdx.x;
    int t = blockIdx.y;
    int n0 = blockIdx.x * 32;

#pragma unroll
    for (int r = 0; r < 4; r++) {
        ((float4*)w1)[tid + r * 256] = ((const float4*)t1w)[tid + r * 256];
        ((float4*)w2)[tid + r * 256] = ((const float4*)t2w)[tid + r * 256];
    }

    int nl = tid >> 3;
    int dg = (tid & 7) * 8;
    int n = n0 + nl;
    size_t rowo = ((size_t)t * N + n) * C;

    float cur[8], prv[8], nxt[8];
#pragma unroll
    for (int qq = 0; qq < 2; qq++) {
        float4 v = *(const float4*)(g_out + rowo + dg + qq * 4);
        cur[qq * 4] = v.x; cur[qq * 4 + 1] = v.y;
        cur[qq * 4 + 2] = v.z; cur[qq * 4 + 3] = v.w;
    }
    if (t >= 1) {
#pragma unroll
        for (int qq = 0; qq < 2; qq++) {
            float4 v = *(const float4*)(g_out + rowo - (size_t)N * C + dg + qq * 4);
            prv[qq * 4] = v.x; prv[qq * 4 + 1] = v.y;
            prv[qq * 4 + 2] = v.z; prv[qq * 4 + 3] = v.w;
        }
    } else {
#pragma unroll
        for (int dd = 0; dd < 8; dd++) prv[dd] = 0.f;
    }
    if (t < T - 1) {
#pragma unroll
        for (int qq = 0; qq < 2; qq++) {
            float4 v = *(const float4*)(g_out + rowo + (size_t)N * C + dg + qq * 4);
            nxt[qq * 4] = v.x; nxt[qq * 4 + 1] = v.y;
            nxt[qq * 4 + 2] = v.z; nxt[qq * 4 + 3] = v.w;
        }
    } else {
#pragma unroll
        for (int dd = 0; dd < 8; dd++) nxt[dd] = 0.f;
    }

    // dots over the 8-lane group owning this node
    float ab = 0.f, bc = 0.f, na = 0.f, nb = 0.f, nc = 0.f;
#pragma unroll
    for (int dd = 0; dd < 8; dd++) {
        ab = fmaf(prv[dd], cur[dd], ab);
        bc = fmaf(cur[dd], nxt[dd], bc);
        na = fmaf(prv[dd], prv[dd], na);
        nb = fmaf(cur[dd], cur[dd], nb);
        nc = fmaf(nxt[dd], nxt[dd], nc);
    }
#pragma unroll
    for (int off = 1; off < 8; off <<= 1) {
        ab += __shfl_xor_sync(0xffffffffu, ab, off);
        bc += __shfl_xor_sync(0xffffffffu, bc, off);
        na += __shfl_xor_sync(0xffffffffu, na, off);
        nb += __shfl_xor_sync(0xffffffffu, nb, off);
        nc += __shfl_xor_sync(0xffffffffu, nc, off);
    }
    float rb = fmaxf(sqrtf(nb), 1e-8f);
    float tem_prev = ab / (fmaxf(sqrtf(na), 1e-8f) * rb);   // == 0 when t==0 (ab=0,na=0->eps)
    float tem_next = bc / (rb * fmaxf(sqrtf(nc), 1e-8f));   // == 0 when t==T-1

    float2* urow = us + nl * C + dg;
#pragma unroll
    for (int dd = 0; dd < 8; dd++)
        urow[dd] = make_float2(tem_next * nxt[dd], tem_prev * prv[dd]);
    __syncthreads();

    unsigned long long acc[4];
#pragma unroll
    for (int qq = 0; qq < 4; qq++)
        acc[qq] = pk2(cur[qq * 2], cur[qq * 2 + 1]);

    const float2* un = us + nl * C;
#pragma unroll 8
    for (int c = 0; c < C; c++) {
        float2 u = un[c];
        unsigned long long u1 = pk2(u.x, u.x);
        unsigned long long u2 = pk2(u.y, u.y);
        const ulonglong2* r1 = (const ulonglong2*)(w1 + c * C + dg);
        const ulonglong2* r2 = (const ulonglong2*)(w2 + c * C + dg);
        ulonglong2 wv1 = r1[0], wv1b = r1[1];
        ulonglong2 wv2 = r2[0], wv2b = r2[1];
        fma2(acc[0], wv1.x, u1);
        fma2(acc[1], wv1.y, u1);
        fma2(acc[2], wv1b.x, u1);
        fma2(acc[3], wv1b.y, u1);
        fma2(acc[0], wv2.x, u2);
        fma2(acc[1], wv2.y, u2);
        fma2(acc[2], wv2b.x, u2);
        fma2(acc[3], wv2b.y, u2);
    }

    float r[8];
#pragma unroll
    for (int qq = 0; qq < 4; qq++) upk2(acc[qq], r[qq * 2], r[qq * 2 + 1]);
#pragma unroll
    for (int qq = 0; qq < 2; qq++) {
        *(float4*)(out + rowo + dg + qq * 4) =
            make_float4(r[qq * 4], r[qq * 4 + 1], r[qq * 4 + 2], r[qq * 4 + 3]);
    }
}

// ============================================================
extern "C" void kernel_launch(void* const* d_in, const int* in_sizes, int n_in,
                              void* d_out, int out_size) {
    const float* x = (const float*)d_in[0];
    const int* adj = (const int*)d_in[1];
    const float* W = (const float*)d_in[2];
    const float* asrc = (const float*)d_in[3];
    const float* adst = (const float*)d_in[4];
    const float* bias = (const float*)d_in[5];
    const float* t1w = (const float*)d_in[6];
    const float* t2w = (const float*)d_in[7];
    float* out = (float*)d_out;

    cudaFuncSetAttribute(kB, cudaFuncAttributeMaxDynamicSharedMemorySize, KB_SMEM);

    kA<<<dim3(N / 64, T), 128>>>(x, W, asrc, adst);
    kB<<<dim3(N / 128, T), 256, KB_SMEM>>>(adj, bias);
    kC<<<dim3(N / 32, T), 256>>>(t1w, t2w, out);
}

// round 7
// speedup vs baseline: 1.9398x; 1.0428x over previous
#include <cuda_runtime.h>
#include <cuda_fp16.h>
#include <math.h>
#include <stdint.h>

#define T 8
#define N 2048
#define F 128
#define C 64

// ---------------- device scratch ----------------
__device__ float g_es[T * N];
__device__ float g_ed[T * N];
__device__ float g_out[T * N * C];
__device__ __half g_hThi[T * C * N];   // h transposed hi fp16: [t][c][n]
__device__ __half g_hTlo[T * C * N];   // residual lo fp16

// ---------------- helpers ----------------
__device__ __forceinline__ uint32_t smem_u32(const void* p) {
    uint32_t a;
    asm("{ .reg .u64 t; cvta.to.shared.u64 t, %1; cvt.u32.u64 %0, t; }"
        : "=r"(a) : "l"(p));
    return a;
}
#define CP_ASYNC16(dst, src) \
    asm volatile("cp.async.cg.shared.global [%0], [%1], 16;" :: "r"(dst), "l"(src) : "memory")
#define CP_COMMIT() asm volatile("cp.async.commit_group;" ::: "memory")
#define CP_WAIT0() asm volatile("cp.async.wait_group 0;" ::: "memory")

__device__ __forceinline__ void ldsm4(uint32_t& r0, uint32_t& r1, uint32_t& r2,
                                      uint32_t& r3, uint32_t addr) {
    asm volatile("ldmatrix.sync.aligned.m8n8.x4.shared.b16 {%0,%1,%2,%3}, [%4];"
                 : "=r"(r0), "=r"(r1), "=r"(r2), "=r"(r3) : "r"(addr));
}
__device__ __forceinline__ void mma16816(float* d, const uint32_t* a, uint32_t b0,
                                         uint32_t b1) {
    asm volatile(
        "mma.sync.aligned.m16n8k16.row.col.f32.f16.f16.f32 "
        "{%0,%1,%2,%3}, {%4,%5,%6,%7}, {%8,%9}, {%0,%1,%2,%3};"
        : "+f"(d[0]), "+f"(d[1]), "+f"(d[2]), "+f"(d[3])
        : "r"(a[0]), "r"(a[1]), "r"(a[2]), "r"(a[3]), "r"(b0), "r"(b1));
}
__device__ __forceinline__ float pv(float2 bb, float Ai, float A2i, float thr,
                                    unsigned mk) {
    float v = (bb.x > thr) ? Ai * bb.x : A2i * bb.y;
    return mk ? v : 0.f;
}
__device__ __forceinline__ uint32_t pack_p(float p0, float p1) {
    __half2 h = __floats2half2_rn(p0, p1);
    return *(uint32_t*)&h;
}

// ---------------- f32x2 helpers ----------------
__device__ __forceinline__ unsigned long long pk2(float lo, float hi) {
    unsigned long long r;
    asm("mov.b64 %0, {%1, %2};" : "=l"(r) : "f"(lo), "f"(hi));
    return r;
}
__device__ __forceinline__ void upk2(unsigned long long v, float& lo, float& hi) {
    asm("mov.b64 {%0, %1}, %2;" : "=f"(lo), "=f"(hi) : "l"(v));
}
__device__ __forceinline__ void fma2(unsigned long long& d, unsigned long long a,
                                     unsigned long long b) {
    asm("fma.rn.f32x2 %0, %1, %2, %0;" : "+l"(d) : "l"(a), "l"(b));
}

// ============================================================
// Kernel A: h = x @ W ; e_s, e_d ; hi/lo fp16 split of h^T.
// 256 threads, 64 rows/block, 1 row per 4 threads (16 c each).
// ============================================================
__global__ __launch_bounds__(256) void kA(const float* __restrict__ x,
                                          const float* __restrict__ W,
                                          const float* __restrict__ asrc,
                                          const float* __restrict__ adst) {
    __shared__ __align__(16) float ws[F * C];         // 32 KB
    __shared__ __align__(16) __half s_hi[C * 64];     // 8 KB
    __shared__ __align__(16) __half s_lo[C * 64];     // 8 KB
    int tid = threadIdx.x;
    int t = blockIdx.y;
    int n0 = blockIdx.x * 64;

    const float4* wg = (const float4*)W;
    float4* ws4 = (float4*)ws;
#pragma unroll
    for (int r = 0; r < 8; r++) ws4[tid + r * 256] = wg[tid + r * 256];
    __syncthreads();

    int row = tid >> 2;
    int cg = (tid & 3) * 16;
    int n = n0 + row;
    const float* xrow = x + ((size_t)t * N + n) * F;

    unsigned long long acc2[8];
#pragma unroll
    for (int q = 0; q < 8; q++) acc2[q] = 0ull;

#pragma unroll 4
    for (int k = 0; k < F; k += 4) {
        float4 xq = *(const float4*)(xrow + k);
        float xv[4] = {xq.x, xq.y, xq.z, xq.w};
#pragma unroll
        for (int s = 0; s < 4; s++) {
            unsigned long long pp = pk2(xv[s], xv[s]);
            const ulonglong2* wr = (const ulonglong2*)(ws + (k + s) * C + cg);
#pragma unroll
            for (int q = 0; q < 4; q++) {
                ulonglong2 wv = wr[q];
                fma2(acc2[2 * q], wv.x, pp);
                fma2(acc2[2 * q + 1], wv.y, pp);
            }
        }
    }

    float hc[16];
#pragma unroll
    for (int q = 0; q < 8; q++) upk2(acc2[q], hc[2 * q], hc[2 * q + 1]);

    // split + transpose into smem
#pragma unroll
    for (int c = 0; c < 16; c++) {
        __half h1 = __float2half_rn(hc[c]);
        s_hi[(cg + c) * 64 + row] = h1;
        s_lo[(cg + c) * 64 + row] = __float2half_rn(hc[c] - __half2float(h1));
    }

    float es = 0.f, ed = 0.f;
#pragma unroll
    for (int c = 0; c < 16; c++) {
        es = fmaf(hc[c], asrc[cg + c], es);
        ed = fmaf(hc[c], adst[cg + c], ed);
    }
    es += __shfl_down_sync(0xffffffffu, es, 1, 4);
    es += __shfl_down_sync(0xffffffffu, es, 2, 4);
    ed += __shfl_down_sync(0xffffffffu, ed, 1, 4);
    ed += __shfl_down_sync(0xffffffffu, ed, 2, 4);
    if ((tid & 3) == 0) {
        g_es[t * N + n] = es;
        g_ed[t * N + n] = ed;
    }
    __syncthreads();

    // writeout: 512 uint4 per array; u: c=u>>3, seg=u&7
    __half* dhi = g_hThi + (size_t)t * C * N;
    __half* dlo = g_hTlo + (size_t)t * C * N;
#pragma unroll
    for (int r = 0; r < 2; r++) {
        int u = tid + r * 256;
        int c = u >> 3, seg = u & 7;
        *(uint4*)(dhi + (size_t)c * N + n0 + seg * 8) = ((const uint4*)s_hi)[u];
        *(uint4*)(dlo + (size_t)c * N + n0 + seg * 8) = ((const uint4*)s_lo)[u];
    }
}

// ============================================================
// Kernel B: masked-softmax aggregation via fp16 HMMA.
// 512 threads = 16 warps. Warp pair (wl, wl+8) shares 16 i-rows,
// kh = wid>>3 selects which half of each 64-j chunk (2 of 4 kt).
// adj staged with 132-int row stride (conflict-free direct reads).
// ============================================================
#define ADJ_STRIDE 132                 // ints; 528 B/row
#define BB_OFF   0                     // 2048 float2 = 16384
#define HS_OFF   16384                 // 2 bufs x (hi,lo) x 9216 = 36864
#define ADJ_OFF  53248                 // 64 x 528 = 33792
#define RED_OFF  87040                 // 512 f32 = 2048
#define BIAS_OFF 89088                 // 64 f32 = 256
#define KB_SMEM  89344
#define DCOMB_OFF ADJ_OFF              // 32 KB overlay after mainloop

__global__ __launch_bounds__(512) void kB(const int* __restrict__ adj,
                                          const float* __restrict__ bias) {
    extern __shared__ __align__(16) char sm[];
    float2* BB = (float2*)(sm + BB_OFF);
    int* adjraw = (int*)(sm + ADJ_OFF);
    float* red = (float*)(sm + RED_OFF);
    float* bias_s = (float*)(sm + BIAS_OFF);
    uint32_t smb = smem_u32(sm);

    int tid = threadIdx.x;
    int wid = tid >> 5;
    int lane = tid & 31;
    int wl = wid & 7;      // row-group
    int kh = wid >> 3;     // kt-half
    int t = blockIdx.y;
    int i0 = blockIdx.x * 128;

    const int* abase = adj + (size_t)t * N * N + i0;
    const __half* hhib = g_hThi + (size_t)t * C * N;
    const __half* hlob = g_hTlo + (size_t)t * C * N;

    // ---- prologue: chunk-0 loads (full 32KB adj tile: 4 cp.async/thread) ----
    {
#pragma unroll
        for (int r = 0; r < 4; r++) {
            int u = tid + r * 512;
            int j = u >> 5, off = u & 31;
            CP_ASYNC16(smb + ADJ_OFF + j * 528 + off * 16,
                       abase + (size_t)j * N + off * 4);
        }
        int c = tid >> 3, o = tid & 7;
        uint32_t doff = (uint32_t)(c * 72 + o * 8) * 2;
        CP_ASYNC16(smb + HS_OFF + doff, hhib + (size_t)c * N + o * 8);
        CP_ASYNC16(smb + HS_OFF + 9216 + doff, hlob + (size_t)c * N + o * 8);
        CP_COMMIT();
    }

    if (tid < 16) ((float4*)bias_s)[tid] = ((const float4*)bias)[tid];

    // ---- e_s staging + max + transform ----
    float lmax = -1e30f;
#pragma unroll
    for (int r = 0; r < 4; r++) {
        float v = g_es[t * N + tid + r * 512];
        BB[tid + r * 512].x = v;
        lmax = fmaxf(lmax, v);
    }
    red[tid] = lmax;
    __syncthreads();
    for (int s = 256; s > 0; s >>= 1) {
        if (tid < s) red[tid] = fmaxf(red[tid], red[tid + s]);
        __syncthreads();
    }
    float esmax = red[0];
#pragma unroll
    for (int r = 0; r < 4; r++) {
        int j = tid + r * 512;
        float v = BB[j].x;
        BB[j] = make_float2(__expf(v - esmax), __expf(0.2f * (v - esmax)));
    }

    // ---- per-row constants ----
    int qd = lane >> 2;
    int il1 = wl * 16 + qd;
    int il2 = il1 + 8;
    int gi1 = i0 + il1, gi2 = i0 + il2;
    float ed1 = g_ed[t * N + gi1], ed2 = g_ed[t * N + gi2];
    float xm1 = ed1 + esmax, xm2 = ed2 + esmax;
    float M1 = fmaxf(xm1, 0.2f * xm1), M2 = fmaxf(xm2, 0.2f * xm2);
    float Ai1 = __expf(xm1 - M1), A2i1 = __expf(0.2f * xm1 - M1), thr1 = __expf(-xm1);
    float Ai2 = __expf(xm2 - M2), A2i2 = __expf(0.2f * xm2 - M2), thr2 = __expf(-xm2);

    float d[8][4];
#pragma unroll
    for (int nt = 0; nt < 8; nt++)
#pragma unroll
        for (int q = 0; q < 4; q++) d[nt][q] = 0.f;
    float sum1 = 0.f, sum2 = 0.f;

    int q = lane & 3;
    int c0j = 2 * q;
    uint32_t rowa = ((lane >> 4) << 3) + (lane & 7);
    uint32_t cola = ((lane >> 3) & 1) * 8;

    __syncthreads();   // BB ready

    int buf = 0;
#pragma unroll 1
    for (int k = 0; k < 32; k++) {
        int j0 = k * 64;
        CP_WAIT0();
        __syncthreads();   // chunk-k data in smem; prior compute done

        // ---- mask bits -> register (direct conflict-free reads) ----
        unsigned mk = 0;
#pragma unroll
        for (int ktl = 0; ktl < 2; ktl++) {
            int jl = (kh * 2 + ktl) * 16 + c0j;
#pragma unroll
            for (int dIdx = 0; dIdx < 4; dIdx++) {
                int dlt = (dIdx & 1) + (dIdx >> 1) * 8;
                int jj = jl + dlt;
                int v1 = adjraw[jj * ADJ_STRIDE + il1];
                int v2 = adjraw[jj * ADJ_STRIDE + il2];
                if (v1 != 0 || (j0 + jj == gi1)) mk |= 1u << (ktl * 8 + dIdx * 2);
                if (v2 != 0 || (j0 + jj == gi2)) mk |= 1u << (ktl * 8 + dIdx * 2 + 1);
            }
        }
        __syncthreads();   // all mask reads done before adj overwrite

        // ---- prefetch chunk k+1 ----
        if (k + 1 < 32) {
            int jn = j0 + 64;
            int nb = buf ^ 1;
#pragma unroll
            for (int r = 0; r < 4; r++) {
                int u = tid + r * 512;
                int j = u >> 5, off = u & 31;
                CP_ASYNC16(smb + ADJ_OFF + j * 528 + off * 16,
                           abase + (size_t)(jn + j) * N + off * 4);
            }
            int c = tid >> 3, o = tid & 7;
            uint32_t doff = (uint32_t)(c * 72 + o * 8) * 2;
            uint32_t hb = smb + HS_OFF + (uint32_t)(nb * 2) * 9216;
            CP_ASYNC16(hb + doff, hhib + (size_t)c * N + jn + o * 8);
            CP_ASYNC16(hb + 9216 + doff, hlob + (size_t)c * N + jn + o * 8);
        }
        CP_COMMIT();

        // ---- compute this warp's two kt sub-chunks ----
        uint32_t hhi_u = smb + HS_OFF + (uint32_t)(buf * 2) * 9216;
        uint32_t hlo_u = hhi_u + 9216;

#pragma unroll
        for (int ktl = 0; ktl < 2; ktl++) {
            int kt = kh * 2 + ktl;
            int jb = j0 + kt * 16 + c0j;
            float2 bA = BB[jb], bBv = BB[jb + 1], bCv = BB[jb + 8], bDv = BB[jb + 9];
            unsigned ml = mk >> (ktl * 8);

            float p10 = pv(bA, Ai1, A2i1, thr1, ml & 1u);
            float p20 = pv(bA, Ai2, A2i2, thr2, (ml >> 1) & 1u);
            float p11 = pv(bBv, Ai1, A2i1, thr1, (ml >> 2) & 1u);
            float p21 = pv(bBv, Ai2, A2i2, thr2, (ml >> 3) & 1u);
            float p18 = pv(bCv, Ai1, A2i1, thr1, (ml >> 4) & 1u);
            float p28 = pv(bCv, Ai2, A2i2, thr2, (ml >> 5) & 1u);
            float p19 = pv(bDv, Ai1, A2i1, thr1, (ml >> 6) & 1u);
            float p29 = pv(bDv, Ai2, A2i2, thr2, (ml >> 7) & 1u);
            sum1 += (p10 + p11) + (p18 + p19);
            sum2 += (p20 + p21) + (p28 + p29);

            uint32_t ap[4];
            ap[0] = pack_p(p10, p11);
            ap[1] = pack_p(p20, p21);
            ap[2] = pack_p(p18, p19);
            ap[3] = pack_p(p28, p29);

            uint32_t lcol = (uint32_t)(kt * 16) + cola;
#pragma unroll
            for (int cg = 0; cg < 4; cg++) {
                uint32_t roff = ((uint32_t)(cg * 16) + rowa) * 144 + lcol * 2;
                uint32_t h0, h1, h2, h3, l0, l1, l2, l3;
                ldsm4(h0, h1, h2, h3, hhi_u + roff);
                ldsm4(l0, l1, l2, l3, hlo_u + roff);
                mma16816(d[cg * 2], ap, h0, h1);
                mma16816(d[cg * 2], ap, l0, l1);
                mma16816(d[cg * 2 + 1], ap, h2, h3);
                mma16816(d[cg * 2 + 1], ap, l2, l3);
            }
        }
        buf ^= 1;
    }

    // ---- combine kt-halves across warp pairs ----
    sum1 += __shfl_xor_sync(0xffffffffu, sum1, 1);
    sum1 += __shfl_xor_sync(0xffffffffu, sum1, 2);
    sum2 += __shfl_xor_sync(0xffffffffu, sum2, 1);
    sum2 += __shfl_xor_sync(0xffffffffu, sum2, 2);

    __syncthreads();   // everyone done with adjraw before overlay
    float* dc = (float*)(sm + DCOMB_OFF);
    float* sums_hi = (float*)(sm + RED_OFF);

    if (kh == 1) {
#pragma unroll
        for (int nt = 0; nt < 8; nt++)
            *(float4*)(dc + wl * 1024 + nt * 128 + lane * 4) =
                make_float4(d[nt][0], d[nt][1], d[nt][2], d[nt][3]);
        if ((lane & 3) == 0) {
            sums_hi[il1] = sum1;
            sums_hi[il2] = sum2;
        }
    }
    __syncthreads();

    if (kh == 0) {
        float st1 = sum1 + sums_hi[il1];
        float st2 = sum2 + sums_hi[il2];
        float s1 = 1.f / st1, s2 = 1.f / st2;

        float* o1 = g_out + ((size_t)t * N + gi1) * C;
        float* o2 = g_out + ((size_t)t * N + gi2) * C;
        int q2 = 2 * q;
#pragma unroll
        for (int nt = 0; nt < 8; nt++) {
            float4 pd = *(const float4*)(dc + wl * 1024 + nt * 128 + lane * 4);
            int c = nt * 8 + q2;
            *(float2*)(o1 + c) = make_float2((d[nt][0] + pd.x) * s1 + bias_s[c],
                                             (d[nt][1] + pd.y) * s1 + bias_s[c + 1]);
            *(float2*)(o2 + c) = make_float2((d[nt][2] + pd.z) * s2 + bias_s[c],
                                             (d[nt][3] + pd.w) * s2 + bias_s[c + 1]);
        }
    }
}

// ============================================================
// Kernel C (merged): inline cosine sims + temporal matvecs.
// ============================================================
__global__ __launch_bounds__(256) void kC(const float* __restrict__ t1w,
                                          const float* __restrict__ t2w,
                                          float* __restrict__ out) {
    __shared__ __align__(16) float w1[C * C];
    __shared__ __align__(16) float w2[C * C];
    __shared__ __align__(16) float2 us[32 * C];
    int tid = threadIdx.x;
    int t = blockIdx.y;
    int n0 = blockIdx.x * 32;

#pragma unroll
    for (int r = 0; r < 4; r++) {
        ((float4*)w1)[tid + r * 256] = ((const float4*)t1w)[tid + r * 256];
        ((float4*)w2)[tid + r * 256] = ((const float4*)t2w)[tid + r * 256];
    }

    int nl = tid >> 3;
    int dg = (tid & 7) * 8;
    int n = n0 + nl;
    size_t rowo = ((size_t)t * N + n) * C;

    float cur[8], prv[8], nxt[8];
#pragma unroll
    for (int qq = 0; qq < 2; qq++) {
        float4 v = *(const float4*)(g_out + rowo + dg + qq * 4);
        cur[qq * 4] = v.x; cur[qq * 4 + 1] = v.y;
        cur[qq * 4 + 2] = v.z; cur[qq * 4 + 3] = v.w;
    }
    if (t >= 1) {
#pragma unroll
        for (int qq = 0; qq < 2; qq++) {
            float4 v = *(const float4*)(g_out + rowo - (size_t)N * C + dg + qq * 4);
            prv[qq * 4] = v.x; prv[qq * 4 + 1] = v.y;
            prv[qq * 4 + 2] = v.z; prv[qq * 4 + 3] = v.w;
        }
    } else {
#pragma unroll
        for (int dd = 0; dd < 8; dd++) prv[dd] = 0.f;
    }
    if (t < T - 1) {
#pragma unroll
        for (int qq = 0; qq < 2; qq++) {
            float4 v = *(const float4*)(g_out + rowo + (size_t)N * C + dg + qq * 4);
            nxt[qq * 4] = v.x; nxt[qq * 4 + 1] = v.y;
            nxt[qq * 4 + 2] = v.z; nxt[qq * 4 + 3] = v.w;
        }
    } else {
#pragma unroll
        for (int dd = 0; dd < 8; dd++) nxt[dd] = 0.f;
    }

    float ab = 0.f, bc = 0.f, na = 0.f, nb = 0.f, nc = 0.f;
#pragma unroll
    for (int dd = 0; dd < 8; dd++) {
        ab = fmaf(prv[dd], cur[dd], ab);
        bc = fmaf(cur[dd], nxt[dd], bc);
        na = fmaf(prv[dd], prv[dd], na);
        nb = fmaf(cur[dd], cur[dd], nb);
        nc = fmaf(nxt[dd], nxt[dd], nc);
    }
#pragma unroll
    for (int off = 1; off < 8; off <<= 1) {
        ab += __shfl_xor_sync(0xffffffffu, ab, off);
        bc += __shfl_xor_sync(0xffffffffu, bc, off);
        na += __shfl_xor_sync(0xffffffffu, na, off);
        nb += __shfl_xor_sync(0xffffffffu, nb, off);
        nc += __shfl_xor_sync(0xffffffffu, nc, off);
    }
    float rb = fmaxf(sqrtf(nb), 1e-8f);
    float tem_prev = ab / (fmaxf(sqrtf(na), 1e-8f) * rb);
    float tem_next = bc / (rb * fmaxf(sqrtf(nc), 1e-8f));

    float2* urow = us + nl * C + dg;
#pragma unroll
    for (int dd = 0; dd < 8; dd++)
        urow[dd] = make_float2(tem_next * nxt[dd], tem_prev * prv[dd]);
    __syncthreads();

    unsigned long long acc[4];
#pragma unroll
    for (int qq = 0; qq < 4; qq++)
        acc[qq] = pk2(cur[qq * 2], cur[qq * 2 + 1]);

    const float2* un = us + nl * C;
#pragma unroll 8
    for (int c = 0; c < C; c++) {
        float2 u = un[c];
        unsigned long long u1 = pk2(u.x, u.x);
        unsigned long long u2 = pk2(u.y, u.y);
        const ulonglong2* r1 = (const ulonglong2*)(w1 + c * C + dg);
        const ulonglong2* r2 = (const ulonglong2*)(w2 + c * C + dg);
        ulonglong2 wv1 = r1[0], wv1b = r1[1];
        ulonglong2 wv2 = r2[0], wv2b = r2[1];
        fma2(acc[0], wv1.x, u1);
        fma2(acc[1], wv1.y, u1);
        fma2(acc[2], wv1b.x, u1);
        fma2(acc[3], wv1b.y, u1);
        fma2(acc[0], wv2.x, u2);
        fma2(acc[1], wv2.y, u2);
        fma2(acc[2], wv2b.x, u2);
        fma2(acc[3], wv2b.y, u2);
    }

    float r[8];
#pragma unroll
    for (int qq = 0; qq < 4; qq++) upk2(acc[qq], r[qq * 2], r[qq * 2 + 1]);
#pragma unroll
    for (int qq = 0; qq < 2; qq++) {
        *(float4*)(out + rowo + dg + qq * 4) =
            make_float4(r[qq * 4], r[qq * 4 + 1], r[qq * 4 + 2], r[qq * 4 + 3]);
    }
}

// ============================================================
extern "C" void kernel_launch(void* const* d_in, const int* in_sizes, int n_in,
                              void* d_out, int out_size) {
    const float* x = (const float*)d_in[0];
    const int* adj = (const int*)d_in[1];
    const float* W = (const float*)d_in[2];
    const float* asrc = (const float*)d_in[3];
    const float* adst = (const float*)d_in[4];
    const float* bias = (const float*)d_in[5];
    const float* t1w = (const float*)d_in[6];
    const float* t2w = (const float*)d_in[7];
    float* out = (float*)d_out;

    cudaFuncSetAttribute(kB, cudaFuncAttributeMaxDynamicSharedMemorySize, KB_SMEM);

    kA<<<dim3(N / 64, T), 256>>>(x, W, asrc, adst);
    kB<<<dim3(N / 128, T), 512, KB_SMEM>>>(adj, bias);
    kC<<<dim3(N / 32, T), 256>>>(t1w, t2w, out);
}

// round 8
// speedup vs baseline: 2.3906x; 1.2324x over previous
#include <cuda_runtime.h>
#include <cuda_fp16.h>
#include <math.h>
#include <stdint.h>

#define T 8
#define N 2048
#define F 128
#define C 64

// ---------------- device scratch ----------------
__device__ float g_es[T * N];
__device__ float g_ed[T * N];
__device__ float g_out[T * N * C];
__device__ __half g_hThi[T * C * N];   // h transposed hi fp16: [t][c][n]
__device__ __half g_hTlo[T * C * N];   // residual lo fp16

// ---------------- helpers ----------------
__device__ __forceinline__ uint32_t smem_u32(const void* p) {
    uint32_t a;
    asm("{ .reg .u64 t; cvta.to.shared.u64 t, %1; cvt.u32.u64 %0, t; }"
        : "=r"(a) : "l"(p));
    return a;
}
#define CP_ASYNC16(dst, src) \
    asm volatile("cp.async.cg.shared.global [%0], [%1], 16;" :: "r"(dst), "l"(src) : "memory")
#define CP_COMMIT() asm volatile("cp.async.commit_group;" ::: "memory")
#define CP_WAIT0() asm volatile("cp.async.wait_group 0;" ::: "memory")
#define CP_WAIT1() asm volatile("cp.async.wait_group 1;" ::: "memory")

__device__ __forceinline__ void ldsm4(uint32_t& r0, uint32_t& r1, uint32_t& r2,
                                      uint32_t& r3, uint32_t addr) {
    asm volatile("ldmatrix.sync.aligned.m8n8.x4.shared.b16 {%0,%1,%2,%3}, [%4];"
                 : "=r"(r0), "=r"(r1), "=r"(r2), "=r"(r3) : "r"(addr));
}
__device__ __forceinline__ void mma16816(float* d, const uint32_t* a, uint32_t b0,
                                         uint32_t b1) {
    asm volatile(
        "mma.sync.aligned.m16n8k16.row.col.f32.f16.f16.f32 "
        "{%0,%1,%2,%3}, {%4,%5,%6,%7}, {%8,%9}, {%0,%1,%2,%3};"
        : "+f"(d[0]), "+f"(d[1]), "+f"(d[2]), "+f"(d[3])
        : "r"(a[0]), "r"(a[1]), "r"(a[2]), "r"(a[3]), "r"(b0), "r"(b1));
}
__device__ __forceinline__ float pv(float2 bb, float Ai, float A2i, float thr,
                                    unsigned mk) {
    float v = (bb.x > thr) ? Ai * bb.x : A2i * bb.y;
    return mk ? v : 0.f;
}
__device__ __forceinline__ uint32_t pack_p(float p0, float p1) {
    __half2 h = __floats2half2_rn(p0, p1);
    return *(uint32_t*)&h;
}

// ---------------- f32x2 helpers ----------------
__device__ __forceinline__ unsigned long long pk2(float lo, float hi) {
    unsigned long long r;
    asm("mov.b64 %0, {%1, %2};" : "=l"(r) : "f"(lo), "f"(hi));
    return r;
}
__device__ __forceinline__ void upk2(unsigned long long v, float& lo, float& hi) {
    asm("mov.b64 {%0, %1}, %2;" : "=f"(lo), "=f"(hi) : "l"(v));
}
__device__ __forceinline__ void fma2(unsigned long long& d, unsigned long long a,
                                     unsigned long long b) {
    asm("fma.rn.f32x2 %0, %1, %2, %0;" : "+l"(d) : "l"(a), "l"(b));
}

// ============================================================
// Kernel A (HMMA): h = x @ W via split-fp16, 3 products.
// CTA: 256 thr (8 warps), 128 rows, K=128, Ncols=64.
// ============================================================
#define KA_WHI  0           // 64 x 136 fp16 = 17408
#define KA_WLO  17408
#define KA_XHI  34816       // 128 x 136 fp16 = 34816
#define KA_XLO  69632
#define KA_WF32 104448      // 8192 f32 = 32768 (temp)
#define KA_HHI  KA_XHI      // overlay after MMA: 64 x 136 fp16
#define KA_HLO  KA_XLO
#define KA_SMEM 137216

__global__ __launch_bounds__(256) void kA(const float* __restrict__ x,
                                          const float* __restrict__ W,
                                          const float* __restrict__ asrc,
                                          const float* __restrict__ adst) {
    extern __shared__ __align__(16) char smA[];
    float* wf = (float*)(smA + KA_WF32);
    __half* whi = (__half*)(smA + KA_WHI);
    __half* wlo = (__half*)(smA + KA_WLO);
    __half* xh = (__half*)(smA + KA_XHI);
    __half* xl = (__half*)(smA + KA_XLO);

    int tid = threadIdx.x;
    int lane = tid & 31;
    int w = tid >> 5;
    int t = blockIdx.y;
    int n0 = blockIdx.x * 128;

    // ---- stage W fp32 ----
#pragma unroll
    for (int r = 0; r < 8; r++)
        ((float4*)wf)[tid + r * 256] = ((const float4*)W)[tid + r * 256];
    __syncthreads();

    // ---- convert+transpose W -> [c][k], stride 136 ----
#pragma unroll
    for (int i = 0; i < 32; i++) {
        int e = tid + i * 256;
        int k = e >> 6, c = e & 63;
        float v = wf[e];
        __half h = __float2half_rn(v);
        whi[c * 136 + k] = h;
        wlo[c * 136 + k] = __float2half_rn(v - __half2float(h));
    }

    // ---- load + convert x -> [row][k] hi/lo, stride 136 ----
    {
        int row = tid >> 1, half = tid & 1;
        const float4* xr4 =
            (const float4*)(x + ((size_t)t * N + n0 + row) * F + half * 64);
        __half* xhp = xh + row * 136 + half * 64;
        __half* xlp = xl + row * 136 + half * 64;
#pragma unroll
        for (int j = 0; j < 16; j++) {
            float4 v = xr4[j];
            __half2 h01 = __floats2half2_rn(v.x, v.y);
            __half2 h23 = __floats2half2_rn(v.z, v.w);
            float2 f01 = __half22float2(h01);
            float2 f23 = __half22float2(h23);
            __half2 l01 = __floats2half2_rn(v.x - f01.x, v.y - f01.y);
            __half2 l23 = __floats2half2_rn(v.z - f23.x, v.w - f23.y);
            *(uint32_t*)(xhp + j * 4) = *(uint32_t*)&h01;
            *(uint32_t*)(xhp + j * 4 + 2) = *(uint32_t*)&h23;
            *(uint32_t*)(xlp + j * 4) = *(uint32_t*)&l01;
            *(uint32_t*)(xlp + j * 4 + 2) = *(uint32_t*)&l23;
        }
    }
    __syncthreads();

    // ---- MMA: 16 rows per warp, 3 split products ----
    float d[8][4];
#pragma unroll
    for (int nt = 0; nt < 8; nt++)
#pragma unroll
        for (int q = 0; q < 4; q++) d[nt][q] = 0.f;

    uint32_t xhi_b = smem_u32(smA + KA_XHI);
    uint32_t xlo_b = smem_u32(smA + KA_XLO);
    uint32_t whi_b = smem_u32(smA + KA_WHI);
    uint32_t wlo_b = smem_u32(smA + KA_WLO);
    int r0 = w * 16;
    uint32_t rowOffA = (lane & 7) + ((lane >> 3) & 1) * 8;
    uint32_t colOffA = (lane >> 4) * 8;
    uint32_t rowB = ((lane >> 4) << 3) + (lane & 7);
    uint32_t colB = ((lane >> 3) & 1) * 8;

#pragma unroll
    for (int ks = 0; ks < 8; ks++) {
        uint32_t kb = ks * 16;
        uint32_t aoff = ((r0 + rowOffA) * 136 + kb + colOffA) * 2;
        uint32_t ahi[4], alo[4];
        ldsm4(ahi[0], ahi[1], ahi[2], ahi[3], xhi_b + aoff);
        ldsm4(alo[0], alo[1], alo[2], alo[3], xlo_b + aoff);
#pragma unroll
        for (int cg = 0; cg < 4; cg++) {
            uint32_t boff = ((cg * 16 + rowB) * 136 + kb + colB) * 2;
            uint32_t h0, h1, h2, h3, l0, l1, l2, l3;
            ldsm4(h0, h1, h2, h3, whi_b + boff);
            ldsm4(l0, l1, l2, l3, wlo_b + boff);
            mma16816(d[cg * 2], ahi, h0, h1);
            mma16816(d[cg * 2], ahi, l0, l1);
            mma16816(d[cg * 2], alo, h0, h1);
            mma16816(d[cg * 2 + 1], ahi, h2, h3);
            mma16816(d[cg * 2 + 1], ahi, l2, l3);
            mma16816(d[cg * 2 + 1], alo, h2, h3);
        }
    }

    // ---- es/ed from f32 frags ----
    int r1 = r0 + (lane >> 2), r2 = r1 + 8;
    float es1 = 0.f, ed1 = 0.f, es2 = 0.f, ed2 = 0.f;
#pragma unroll
    for (int nt = 0; nt < 8; nt++) {
        int c = nt * 8 + 2 * (lane & 3);
        float a0 = asrc[c], a1 = asrc[c + 1];
        float b0 = adst[c], b1 = adst[c + 1];
        es1 += d[nt][0] * a0 + d[nt][1] * a1;
        ed1 += d[nt][0] * b0 + d[nt][1] * b1;
        es2 += d[nt][2] * a0 + d[nt][3] * a1;
        ed2 += d[nt][2] * b0 + d[nt][3] * b1;
    }
#pragma unroll
    for (int off = 1; off < 4; off <<= 1) {
        es1 += __shfl_xor_sync(0xffffffffu, es1, off);
        ed1 += __shfl_xor_sync(0xffffffffu, ed1, off);
        es2 += __shfl_xor_sync(0xffffffffu, es2, off);
        ed2 += __shfl_xor_sync(0xffffffffu, ed2, off);
    }
    if ((lane & 3) == 0) {
        g_es[t * N + n0 + r1] = es1;
        g_ed[t * N + n0 + r1] = ed1;
        g_es[t * N + n0 + r2] = es2;
        g_ed[t * N + n0 + r2] = ed2;
    }

    // ---- h hi/lo transpose into smem (overlay x region) ----
    __syncthreads();
    __half* hh = (__half*)(smA + KA_HHI);
    __half* hl = (__half*)(smA + KA_HLO);
#pragma unroll
    for (int nt = 0; nt < 8; nt++) {
        int c = nt * 8 + 2 * (lane & 3);
        float v;
        __half h;
        v = d[nt][0]; h = __float2half_rn(v);
        hh[c * 136 + r1] = h; hl[c * 136 + r1] = __float2half_rn(v - __half2float(h));
        v = d[nt][1]; h = __float2half_rn(v);
        hh[(c + 1) * 136 + r1] = h; hl[(c + 1) * 136 + r1] = __float2half_rn(v - __half2float(h));
        v = d[nt][2]; h = __float2half_rn(v);
        hh[c * 136 + r2] = h; hl[c * 136 + r2] = __float2half_rn(v - __half2float(h));
        v = d[nt][3]; h = __float2half_rn(v);
        hh[(c + 1) * 136 + r2] = h; hl[(c + 1) * 136 + r2] = __float2half_rn(v - __half2float(h));
    }
    __syncthreads();

    // ---- coalesced writeout ----
    __half* dhi = g_hThi + (size_t)t * C * N;
    __half* dlo = g_hTlo + (size_t)t * C * N;
#pragma unroll
    for (int i = 0; i < 4; i++) {
        int u = tid + i * 256;
        int c = u >> 4, seg = u & 15;
        *(uint4*)(dhi + (size_t)c * N + n0 + seg * 8) = *(uint4*)(hh + c * 136 + seg * 8);
        *(uint4*)(dlo + (size_t)c * N + n0 + seg * 8) = *(uint4*)(hl + c * 136 + seg * 8);
    }
}

// ============================================================
// Kernel B: masked-softmax aggregation via fp16 HMMA.
// 512 threads = 16 warps, kt-split warp pairs, 2-deep cp.async
// pipeline with double-buffered adj AND H tiles.
// ============================================================
#define ADJ_STRIDE 132
#define ADJ_BYTES  33792
#define BB_OFF   0                     // 16384
#define HS_OFF   16384                 // 2 bufs x (hi,lo) x 9216 = 36864
#define ADJ_OFF  53248                 // 2 x 33792 = 67584
#define RED_OFF  120832                // 2048
#define BIAS_OFF 122880                // 256
#define KB_SMEM  123136
#define DCOMB_OFF ADJ_OFF

__global__ __launch_bounds__(512) void kB(const int* __restrict__ adj,
                                          const float* __restrict__ bias) {
    extern __shared__ __align__(16) char sm[];
    float2* BB = (float2*)(sm + BB_OFF);
    float* red = (float*)(sm + RED_OFF);
    float* bias_s = (float*)(sm + BIAS_OFF);
    uint32_t smb = smem_u32(sm);

    int tid = threadIdx.x;
    int wid = tid >> 5;
    int lane = tid & 31;
    int wl = wid & 7;
    int kh = wid >> 3;
    int t = blockIdx.y;
    int i0 = blockIdx.x * 128;

    const int* abase = adj + (size_t)t * N * N + i0;
    const __half* hhib = g_hThi + (size_t)t * C * N;
    const __half* hlob = g_hTlo + (size_t)t * C * N;

    // ---- prologue: chunks 0 and 1 ----
#pragma unroll
    for (int b = 0; b < 2; b++) {
#pragma unroll
        for (int r = 0; r < 4; r++) {
            int u = tid + r * 512;
            int j = u >> 5, off = u & 31;
            CP_ASYNC16(smb + ADJ_OFF + b * ADJ_BYTES + j * 528 + off * 16,
                       abase + (size_t)(b * 64 + j) * N + off * 4);
        }
        int c = tid >> 3, o = tid & 7;
        uint32_t doff = (uint32_t)(c * 72 + o * 8) * 2;
        uint32_t hb = smb + HS_OFF + (uint32_t)b * 18432;
        CP_ASYNC16(hb + doff, hhib + (size_t)c * N + b * 64 + o * 8);
        CP_ASYNC16(hb + 9216 + doff, hlob + (size_t)c * N + b * 64 + o * 8);
        CP_COMMIT();
    }

    if (tid < 16) ((float4*)bias_s)[tid] = ((const float4*)bias)[tid];

    // ---- e_s staging + max + transform ----
    float lmax = -1e30f;
#pragma unroll
    for (int r = 0; r < 4; r++) {
        float v = g_es[t * N + tid + r * 512];
        BB[tid + r * 512].x = v;
        lmax = fmaxf(lmax, v);
    }
    red[tid] = lmax;
    __syncthreads();
    for (int s = 256; s > 0; s >>= 1) {
        if (tid < s) red[tid] = fmaxf(red[tid], red[tid + s]);
        __syncthreads();
    }
    float esmax = red[0];
#pragma unroll
    for (int r = 0; r < 4; r++) {
        int j = tid + r * 512;
        float v = BB[j].x;
        BB[j] = make_float2(__expf(v - esmax), __expf(0.2f * (v - esmax)));
    }

    // ---- per-row constants ----
    int qd = lane >> 2;
    int il1 = wl * 16 + qd;
    int il2 = il1 + 8;
    int gi1 = i0 + il1, gi2 = i0 + il2;
    float ed1 = g_ed[t * N + gi1], ed2 = g_ed[t * N + gi2];
    float xm1 = ed1 + esmax, xm2 = ed2 + esmax;
    float M1 = fmaxf(xm1, 0.2f * xm1), M2 = fmaxf(xm2, 0.2f * xm2);
    float Ai1 = __expf(xm1 - M1), A2i1 = __expf(0.2f * xm1 - M1), thr1 = __expf(-xm1);
    float Ai2 = __expf(xm2 - M2), A2i2 = __expf(0.2f * xm2 - M2), thr2 = __expf(-xm2);

    float d[8][4];
#pragma unroll
    for (int nt = 0; nt < 8; nt++)
#pragma unroll
        for (int q = 0; q < 4; q++) d[nt][q] = 0.f;
    float sum1 = 0.f, sum2 = 0.f;

    int q = lane & 3;
    int c0j = 2 * q;
    uint32_t rowa = ((lane >> 4) << 3) + (lane & 7);
    uint32_t cola = ((lane >> 3) & 1) * 8;

    __syncthreads();   // BB ready

#pragma unroll 1
    for (int k = 0; k < 32; k++) {
        int j0 = k * 64;
        int bufk = k & 1;
        if (k < 31) { CP_WAIT1(); } else { CP_WAIT0(); }
        __syncthreads();   // chunk-k data visible

        int* adjraw = (int*)(sm + ADJ_OFF + bufk * ADJ_BYTES);

        // ---- mask bits -> register ----
        unsigned mk = 0;
#pragma unroll
        for (int ktl = 0; ktl < 2; ktl++) {
            int jl = (kh * 2 + ktl) * 16 + c0j;
#pragma unroll
            for (int dIdx = 0; dIdx < 4; dIdx++) {
                int dlt = (dIdx & 1) + (dIdx >> 1) * 8;
                int jj = jl + dlt;
                int v1 = adjraw[jj * ADJ_STRIDE + il1];
                int v2 = adjraw[jj * ADJ_STRIDE + il2];
                if (v1 != 0 || (j0 + jj == gi1)) mk |= 1u << (ktl * 8 + dIdx * 2);
                if (v2 != 0 || (j0 + jj == gi2)) mk |= 1u << (ktl * 8 + dIdx * 2 + 1);
            }
        }

        // ---- compute ----
        uint32_t hhi_u = smb + HS_OFF + (uint32_t)bufk * 18432;
        uint32_t hlo_u = hhi_u + 9216;

#pragma unroll
        for (int ktl = 0; ktl < 2; ktl++) {
            int kt = kh * 2 + ktl;
            int jb = j0 + kt * 16 + c0j;
            float2 bA = BB[jb], bBv = BB[jb + 1], bCv = BB[jb + 8], bDv = BB[jb + 9];
            unsigned ml = mk >> (ktl * 8);

            float p10 = pv(bA, Ai1, A2i1, thr1, ml & 1u);
            float p20 = pv(bA, Ai2, A2i2, thr2, (ml >> 1) & 1u);
            float p11 = pv(bBv, Ai1, A2i1, thr1, (ml >> 2) & 1u);
            float p21 = pv(bBv, Ai2, A2i2, thr2, (ml >> 3) & 1u);
            float p18 = pv(bCv, Ai1, A2i1, thr1, (ml >> 4) & 1u);
            float p28 = pv(bCv, Ai2, A2i2, thr2, (ml >> 5) & 1u);
            float p19 = pv(bDv, Ai1, A2i1, thr1, (ml >> 6) & 1u);
            float p29 = pv(bDv, Ai2, A2i2, thr2, (ml >> 7) & 1u);
            sum1 += (p10 + p11) + (p18 + p19);
            sum2 += (p20 + p21) + (p28 + p29);

            uint32_t ap[4];
            ap[0] = pack_p(p10, p11);
            ap[1] = pack_p(p20, p21);
            ap[2] = pack_p(p18, p19);
            ap[3] = pack_p(p28, p29);

            uint32_t lcol = (uint32_t)(kt * 16) + cola;
#pragma unroll
            for (int cg = 0; cg < 4; cg++) {
                uint32_t roff = ((uint32_t)(cg * 16) + rowa) * 144 + lcol * 2;
                uint32_t h0, h1, h2, h3, l0, l1, l2, l3;
                ldsm4(h0, h1, h2, h3, hhi_u + roff);
                ldsm4(l0, l1, l2, l3, hlo_u + roff);
                mma16816(d[cg * 2], ap, h0, h1);
                mma16816(d[cg * 2], ap, l0, l1);
                mma16816(d[cg * 2 + 1], ap, h2, h3);
                mma16816(d[cg * 2 + 1], ap, l2, l3);
            }
        }
        __syncthreads();   // buffer bufk fully consumed

        // ---- refill bufk with chunk k+2 ----
        if (k + 2 < 32) {
            int jn = j0 + 128;
#pragma unroll
            for (int r = 0; r < 4; r++) {
                int u = tid + r * 512;
                int j = u >> 5, off = u & 31;
                CP_ASYNC16(smb + ADJ_OFF + bufk * ADJ_BYTES + j * 528 + off * 16,
                           abase + (size_t)(jn + j) * N + off * 4);
            }
            int c = tid >> 3, o = tid & 7;
            uint32_t doff = (uint32_t)(c * 72 + o * 8) * 2;
            uint32_t hb = smb + HS_OFF + (uint32_t)bufk * 18432;
            CP_ASYNC16(hb + doff, hhib + (size_t)c * N + jn + o * 8);
            CP_ASYNC16(hb + 9216 + doff, hlob + (size_t)c * N + jn + o * 8);
            CP_COMMIT();
        }
    }

    // ---- combine kt-halves ----
    sum1 += __shfl_xor_sync(0xffffffffu, sum1, 1);
    sum1 += __shfl_xor_sync(0xffffffffu, sum1, 2);
    sum2 += __shfl_xor_sync(0xffffffffu, sum2, 1);
    sum2 += __shfl_xor_sync(0xffffffffu, sum2, 2);

    __syncthreads();
    float* dc = (float*)(sm + DCOMB_OFF);
    float* sums_hi = (float*)(sm + RED_OFF);

    if (kh == 1) {
#pragma unroll
        for (int nt = 0; nt < 8; nt++)
            *(float4*)(dc + wl * 1024 + nt * 128 + lane * 4) =
                make_float4(d[nt][0], d[nt][1], d[nt][2], d[nt][3]);
        if ((lane & 3) == 0) {
            sums_hi[il1] = sum1;
            sums_hi[il2] = sum2;
        }
    }
    __syncthreads();

    if (kh == 0) {
        float st1 = sum1 + sums_hi[il1];
        float st2 = sum2 + sums_hi[il2];
        float s1 = 1.f / st1, s2 = 1.f / st2;

        float* o1 = g_out + ((size_t)t * N + gi1) * C;
        float* o2 = g_out + ((size_t)t * N + gi2) * C;
        int q2 = 2 * q;
#pragma unroll
        for (int nt = 0; nt < 8; nt++) {
            float4 pd = *(const float4*)(dc + wl * 1024 + nt * 128 + lane * 4);
            int c = nt * 8 + q2;
            *(float2*)(o1 + c) = make_float2((d[nt][0] + pd.x) * s1 + bias_s[c],
                                             (d[nt][1] + pd.y) * s1 + bias_s[c + 1]);
            *(float2*)(o2 + c) = make_float2((d[nt][2] + pd.z) * s2 + bias_s[c],
                                             (d[nt][3] + pd.w) * s2 + bias_s[c + 1]);
        }
    }
}

// ============================================================
// Kernel C (merged): inline cosine sims + temporal matvecs.
// ============================================================
__global__ __launch_bounds__(256) void kC(const float* __restrict__ t1w,
                                          const float* __restrict__ t2w,
                                          float* __restrict__ out) {
    __shared__ __align__(16) float w1[C * C];
    __shared__ __align__(16) float w2[C * C];
    __shared__ __align__(16) float2 us[32 * C];
    int tid = threadIdx.x;
    int t = blockIdx.y;
    int n0 = blockIdx.x * 32;

#pragma unroll
    for (int r = 0; r < 4; r++) {
        ((float4*)w1)[tid + r * 256] = ((const float4*)t1w)[tid + r * 256];
        ((float4*)w2)[tid + r * 256] = ((const float4*)t2w)[tid + r * 256];
    }

    int nl = tid >> 3;
    int dg = (tid & 7) * 8;
    int n = n0 + nl;
    size_t rowo = ((size_t)t * N + n) * C;

    float cur[8], prv[8], nxt[8];
#pragma unroll
    for (int qq = 0; qq < 2; qq++) {
        float4 v = *(const float4*)(g_out + rowo + dg + qq * 4);
        cur[qq * 4] = v.x; cur[qq * 4 + 1] = v.y;
        cur[qq * 4 + 2] = v.z; cur[qq * 4 + 3] = v.w;
    }
    if (t >= 1) {
#pragma unroll
        for (int qq = 0; qq < 2; qq++) {
            float4 v = *(const float4*)(g_out + rowo - (size_t)N * C + dg + qq * 4);
            prv[qq * 4] = v.x; prv[qq * 4 + 1] = v.y;
            prv[qq * 4 + 2] = v.z; prv[qq * 4 + 3] = v.w;
        }
    } else {
#pragma unroll
        for (int dd = 0; dd < 8; dd++) prv[dd] = 0.f;
    }
    if (t < T - 1) {
#pragma unroll
        for (int qq = 0; qq < 2; qq++) {
            float4 v = *(const float4*)(g_out + rowo + (size_t)N * C + dg + qq * 4);
            nxt[qq * 4] = v.x; nxt[qq * 4 + 1] = v.y;
            nxt[qq * 4 + 2] = v.z; nxt[qq * 4 + 3] = v.w;
        }
    } else {
#pragma unroll
        for (int dd = 0; dd < 8; dd++) nxt[dd] = 0.f;
    }

    float ab = 0.f, bc = 0.f, na = 0.f, nb = 0.f, nc = 0.f;
#pragma unroll
    for (int dd = 0; dd < 8; dd++) {
        ab = fmaf(prv[dd], cur[dd], ab);
        bc = fmaf(cur[dd], nxt[dd], bc);
        na = fmaf(prv[dd], prv[dd], na);
        nb = fmaf(cur[dd], cur[dd], nb);
        nc = fmaf(nxt[dd], nxt[dd], nc);
    }
#pragma unroll
    for (int off = 1; off < 8; off <<= 1) {
        ab += __shfl_xor_sync(0xffffffffu, ab, off);
        bc += __shfl_xor_sync(0xffffffffu, bc, off);
        na += __shfl_xor_sync(0xffffffffu, na, off);
        nb += __shfl_xor_sync(0xffffffffu, nb, off);
        nc += __shfl_xor_sync(0xffffffffu, nc, off);
    }
    float rb = fmaxf(sqrtf(nb), 1e-8f);
    float tem_prev = ab / (fmaxf(sqrtf(na), 1e-8f) * rb);
    float tem_next = bc / (rb * fmaxf(sqrtf(nc), 1e-8f));

    float2* urow = us + nl * C + dg;
#pragma unroll
    for (int dd = 0; dd < 8; dd++)
        urow[dd] = make_float2(tem_next * nxt[dd], tem_prev * prv[dd]);
    __syncthreads();

    unsigned long long acc[4];
#pragma unroll
    for (int qq = 0; qq < 4; qq++)
        acc[qq] = pk2(cur[qq * 2], cur[qq * 2 + 1]);

    const float2* un = us + nl * C;
#pragma unroll 8
    for (int c = 0; c < C; c++) {
        float2 u = un[c];
        unsigned long long u1 = pk2(u.x, u.x);
        unsigned long long u2 = pk2(u.y, u.y);
        const ulonglong2* r1 = (const ulonglong2*)(w1 + c * C + dg);
        const ulonglong2* r2 = (const ulonglong2*)(w2 + c * C + dg);
        ulonglong2 wv1 = r1[0], wv1b = r1[1];
        ulonglong2 wv2 = r2[0], wv2b = r2[1];
        fma2(acc[0], wv1.x, u1);
        fma2(acc[1], wv1.y, u1);
        fma2(acc[2], wv1b.x, u1);
        fma2(acc[3], wv1b.y, u1);
        fma2(acc[0], wv2.x, u2);
        fma2(acc[1], wv2.y, u2);
        fma2(acc[2], wv2b.x, u2);
        fma2(acc[3], wv2b.y, u2);
    }

    float r[8];
#pragma unroll
    for (int qq = 0; qq < 4; qq++) upk2(acc[qq], r[qq * 2], r[qq * 2 + 1]);
#pragma unroll
    for (int qq = 0; qq < 2; qq++) {
        *(float4*)(out + rowo + dg + qq * 4) =
            make_float4(r[qq * 4], r[qq * 4 + 1], r[qq * 4 + 2], r[qq * 4 + 3]);
    }
}

// ============================================================
extern "C" void kernel_launch(void* const* d_in, const int* in_sizes, int n_in,
                              void* d_out, int out_size) {
    const float* x = (const float*)d_in[0];
    const int* adj = (const int*)d_in[1];
    const float* W = (const float*)d_in[2];
    const float* asrc = (const float*)d_in[3];
    const float* adst = (const float*)d_in[4];
    const float* bias = (const float*)d_in[5];
    const float* t1w = (const float*)d_in[6];
    const float* t2w = (const float*)d_in[7];
    float* out = (float*)d_out;

    cudaFuncSetAttribute(kA, cudaFuncAttributeMaxDynamicSharedMemorySize, KA_SMEM);
    cudaFuncSetAttribute(kB, cudaFuncAttributeMaxDynamicSharedMemorySize, KB_SMEM);

    kA<<<dim3(N / 128, T), 256, KA_SMEM>>>(x, W, asrc, adst);
    kB<<<dim3(N / 128, T), 512, KB_SMEM>>>(adj, bias);
    kC<<<dim3(N / 32, T), 256>>>(t1w, t2w, out);
}

// round 9
// speedup vs baseline: 2.7090x; 1.1332x over previous
#include <cuda_runtime.h>
#include <cuda_fp16.h>
#include <math.h>
#include <stdint.h>

#define T 8
#define N 2048
#define F 128
#define C 64

// ---------------- device scratch ----------------
__device__ float g_es[T * N];
__device__ float g_ed[T * N];
__device__ float g_out[T * N * C];
__device__ __half g_hThi[T * C * N];   // h transposed fp16: [t][c][n]

// ---------------- helpers ----------------
__device__ __forceinline__ uint32_t smem_u32(const void* p) {
    uint32_t a;
    asm("{ .reg .u64 t; cvta.to.shared.u64 t, %1; cvt.u32.u64 %0, t; }"
        : "=r"(a) : "l"(p));
    return a;
}
#define CP_ASYNC16(dst, src) \
    asm volatile("cp.async.cg.shared.global [%0], [%1], 16;" :: "r"(dst), "l"(src) : "memory")
#define CP_COMMIT() asm volatile("cp.async.commit_group;" ::: "memory")
#define CP_WAIT0() asm volatile("cp.async.wait_group 0;" ::: "memory")
#define CP_WAIT1() asm volatile("cp.async.wait_group 1;" ::: "memory")

__device__ __forceinline__ void ldsm4(uint32_t& r0, uint32_t& r1, uint32_t& r2,
                                      uint32_t& r3, uint32_t addr) {
    asm volatile("ldmatrix.sync.aligned.m8n8.x4.shared.b16 {%0,%1,%2,%3}, [%4];"
                 : "=r"(r0), "=r"(r1), "=r"(r2), "=r"(r3) : "r"(addr));
}
__device__ __forceinline__ void mma16816(float* d, const uint32_t* a, uint32_t b0,
                                         uint32_t b1) {
    asm volatile(
        "mma.sync.aligned.m16n8k16.row.col.f32.f16.f16.f32 "
        "{%0,%1,%2,%3}, {%4,%5,%6,%7}, {%8,%9}, {%0,%1,%2,%3};"
        : "+f"(d[0]), "+f"(d[1]), "+f"(d[2]), "+f"(d[3])
        : "r"(a[0]), "r"(a[1]), "r"(a[2]), "r"(a[3]), "r"(b0), "r"(b1));
}
__device__ __forceinline__ uint32_t pack_p(float p0, float p1) {
    __half2 h = __floats2half2_rn(p0, p1);
    return *(uint32_t*)&h;
}

// ---------------- f32x2 helpers ----------------
__device__ __forceinline__ unsigned long long pk2(float lo, float hi) {
    unsigned long long r;
    asm("mov.b64 %0, {%1, %2};" : "=l"(r) : "f"(lo), "f"(hi));
    return r;
}
__device__ __forceinline__ void upk2(unsigned long long v, float& lo, float& hi) {
    asm("mov.b64 {%0, %1}, %2;" : "=f"(lo), "=f"(hi) : "l"(v));
}
__device__ __forceinline__ void fma2(unsigned long long& d, unsigned long long a,
                                     unsigned long long b) {
    asm("fma.rn.f32x2 %0, %1, %2, %0;" : "+l"(d) : "l"(a), "l"(b));
}

// ============================================================
// Kernel A (HMMA): h = x @ W via split-fp16 (3 products).
// CTA: 128 thr (4 warps), 64 rows. grid (N/64, T) = 256 CTAs.
// ============================================================
#define KA_WHI  0            // 64 x 136 fp16 = 17408
#define KA_WLO  17408
#define KA_XHI  34816        // 64 x 136 fp16 = 17408
#define KA_XLO  52224
#define KA_WF32 69632        // 8192 f32 = 32768
#define KA_HHI  KA_XHI       // overlay after MMA
#define KA_SMEM 102400

__global__ __launch_bounds__(128) void kA(const float* __restrict__ x,
                                          const float* __restrict__ W,
                                          const float* __restrict__ asrc,
                                          const float* __restrict__ adst) {
    extern __shared__ __align__(16) char smA[];
    float* wf = (float*)(smA + KA_WF32);
    __half* whi = (__half*)(smA + KA_WHI);
    __half* wlo = (__half*)(smA + KA_WLO);
    __half* xh = (__half*)(smA + KA_XHI);
    __half* xl = (__half*)(smA + KA_XLO);

    int tid = threadIdx.x;
    int lane = tid & 31;
    int w = tid >> 5;
    int t = blockIdx.y;
    int n0 = blockIdx.x * 64;

    // ---- stage W fp32 ----
#pragma unroll
    for (int r = 0; r < 16; r++)
        ((float4*)wf)[tid + r * 128] = ((const float4*)W)[tid + r * 128];
    __syncthreads();

    // ---- convert+transpose W -> [c][k], stride 136 ----
#pragma unroll
    for (int i = 0; i < 64; i++) {
        int e = tid + i * 128;
        int k = e >> 6, c = e & 63;
        float v = wf[e];
        __half h = __float2half_rn(v);
        whi[c * 136 + k] = h;
        wlo[c * 136 + k] = __float2half_rn(v - __half2float(h));
    }

    // ---- load + convert x -> [row][k] hi/lo, stride 136 ----
    {
        int row = tid >> 1, half = tid & 1;
        const float4* xr4 =
            (const float4*)(x + ((size_t)t * N + n0 + row) * F + half * 64);
        __half* xhp = xh + row * 136 + half * 64;
        __half* xlp = xl + row * 136 + half * 64;
#pragma unroll
        for (int j = 0; j < 16; j++) {
            float4 v = xr4[j];
            __half2 h01 = __floats2half2_rn(v.x, v.y);
            __half2 h23 = __floats2half2_rn(v.z, v.w);
            float2 f01 = __half22float2(h01);
            float2 f23 = __half22float2(h23);
            __half2 l01 = __floats2half2_rn(v.x - f01.x, v.y - f01.y);
            __half2 l23 = __floats2half2_rn(v.z - f23.x, v.w - f23.y);
            *(uint32_t*)(xhp + j * 4) = *(uint32_t*)&h01;
            *(uint32_t*)(xhp + j * 4 + 2) = *(uint32_t*)&h23;
            *(uint32_t*)(xlp + j * 4) = *(uint32_t*)&l01;
            *(uint32_t*)(xlp + j * 4 + 2) = *(uint32_t*)&l23;
        }
    }
    __syncthreads();

    // ---- MMA: 16 rows per warp, 3 split products ----
    float d[8][4];
#pragma unroll
    for (int nt = 0; nt < 8; nt++)
#pragma unroll
        for (int q = 0; q < 4; q++) d[nt][q] = 0.f;

    uint32_t xhi_b = smem_u32(smA + KA_XHI);
    uint32_t xlo_b = smem_u32(smA + KA_XLO);
    uint32_t whi_b = smem_u32(smA + KA_WHI);
    uint32_t wlo_b = smem_u32(smA + KA_WLO);
    int r0 = w * 16;
    uint32_t rowOffA = (lane & 7) + ((lane >> 3) & 1) * 8;
    uint32_t colOffA = (lane >> 4) * 8;
    uint32_t rowB = ((lane >> 4) << 3) + (lane & 7);
    uint32_t colB = ((lane >> 3) & 1) * 8;

#pragma unroll
    for (int ks = 0; ks < 8; ks++) {
        uint32_t kb = ks * 16;
        uint32_t aoff = ((r0 + rowOffA) * 136 + kb + colOffA) * 2;
        uint32_t ahi[4], alo[4];
        ldsm4(ahi[0], ahi[1], ahi[2], ahi[3], xhi_b + aoff);
        ldsm4(alo[0], alo[1], alo[2], alo[3], xlo_b + aoff);
#pragma unroll
        for (int cg = 0; cg < 4; cg++) {
            uint32_t boff = ((cg * 16 + rowB) * 136 + kb + colB) * 2;
            uint32_t h0, h1, h2, h3, l0, l1, l2, l3;
            ldsm4(h0, h1, h2, h3, whi_b + boff);
            ldsm4(l0, l1, l2, l3, wlo_b + boff);
            mma16816(d[cg * 2], ahi, h0, h1);
            mma16816(d[cg * 2], ahi, l0, l1);
            mma16816(d[cg * 2], alo, h0, h1);
            mma16816(d[cg * 2 + 1], ahi, h2, h3);
            mma16816(d[cg * 2 + 1], ahi, l2, l3);
            mma16816(d[cg * 2 + 1], alo, h2, h3);
        }
    }

    // ---- es/ed from f32 frags ----
    int r1 = r0 + (lane >> 2), r2 = r1 + 8;
    float es1 = 0.f, ed1 = 0.f, es2 = 0.f, ed2 = 0.f;
#pragma unroll
    for (int nt = 0; nt < 8; nt++) {
        int c = nt * 8 + 2 * (lane & 3);
        float a0 = asrc[c], a1 = asrc[c + 1];
        float b0 = adst[c], b1 = adst[c + 1];
        es1 += d[nt][0] * a0 + d[nt][1] * a1;
        ed1 += d[nt][0] * b0 + d[nt][1] * b1;
        es2 += d[nt][2] * a0 + d[nt][3] * a1;
        ed2 += d[nt][2] * b0 + d[nt][3] * b1;
    }
#pragma unroll
    for (int off = 1; off < 4; off <<= 1) {
        es1 += __shfl_xor_sync(0xffffffffu, es1, off);
        ed1 += __shfl_xor_sync(0xffffffffu, ed1, off);
        es2 += __shfl_xor_sync(0xffffffffu, es2, off);
        ed2 += __shfl_xor_sync(0xffffffffu, ed2, off);
    }
    if ((lane & 3) == 0) {
        g_es[t * N + n0 + r1] = es1;
        g_ed[t * N + n0 + r1] = ed1;
        g_es[t * N + n0 + r2] = es2;
        g_ed[t * N + n0 + r2] = ed2;
    }

    // ---- h (hi only) transpose into smem, overlay x region ----
    __syncthreads();
    __half* hh = (__half*)(smA + KA_HHI);
#pragma unroll
    for (int nt = 0; nt < 8; nt++) {
        int c = nt * 8 + 2 * (lane & 3);
        hh[c * 136 + r1] = __float2half_rn(d[nt][0]);
        hh[(c + 1) * 136 + r1] = __float2half_rn(d[nt][1]);
        hh[c * 136 + r2] = __float2half_rn(d[nt][2]);
        hh[(c + 1) * 136 + r2] = __float2half_rn(d[nt][3]);
    }
    __syncthreads();

    // ---- coalesced writeout: 64 c x 64 n halves = 512 uint4 ----
    __half* dhi = g_hThi + (size_t)t * C * N;
#pragma unroll
    for (int i = 0; i < 4; i++) {
        int u = tid + i * 128;
        int c = u >> 3, seg = u & 7;
        *(uint4*)(dhi + (size_t)c * N + n0 + seg * 8) = *(uint4*)(hh + c * 136 + seg * 8);
    }
}

// ============================================================
// Kernel B: masked-softmax aggregation via fp16 HMMA (hi-only H).
// 512 threads = 16 warps, kt-split warp pairs, 2-deep pipeline.
// Fused mask+P build; p = max(Ai*Bx, A2i*By) (exact lrelu-exp).
// ============================================================
#define ADJ_STRIDE 132
#define ADJ_BYTES  33792
#define BB_OFF   0                     // 16384
#define HS_OFF   16384                 // 2 bufs x 9216 = 18432
#define ADJ_OFF  34816                 // 2 x 33792 = 67584
#define RED_OFF  102400                // 2048
#define BIAS_OFF 104448                // 256
#define KB_SMEM  104704
#define DCOMB_OFF ADJ_OFF

__global__ __launch_bounds__(512) void kB(const int* __restrict__ adj,
                                          const float* __restrict__ bias) {
    extern __shared__ __align__(16) char sm[];
    float2* BB = (float2*)(sm + BB_OFF);
    float* red = (float*)(sm + RED_OFF);
    float* bias_s = (float*)(sm + BIAS_OFF);
    uint32_t smb = smem_u32(sm);

    int tid = threadIdx.x;
    int wid = tid >> 5;
    int lane = tid & 31;
    int wl = wid & 7;
    int kh = wid >> 3;
    int t = blockIdx.y;
    int i0 = blockIdx.x * 128;

    const int* abase = adj + (size_t)t * N * N + i0;
    const __half* hhib = g_hThi + (size_t)t * C * N;

    // ---- prologue: chunks 0 and 1 ----
#pragma unroll
    for (int b = 0; b < 2; b++) {
#pragma unroll
        for (int r = 0; r < 4; r++) {
            int u = tid + r * 512;
            int j = u >> 5, off = u & 31;
            CP_ASYNC16(smb + ADJ_OFF + b * ADJ_BYTES + j * 528 + off * 16,
                       abase + (size_t)(b * 64 + j) * N + off * 4);
        }
        int c = tid >> 3, o = tid & 7;
        uint32_t doff = (uint32_t)(c * 72 + o * 8) * 2;
        CP_ASYNC16(smb + HS_OFF + b * 9216 + doff, hhib + (size_t)c * N + b * 64 + o * 8);
        CP_COMMIT();
    }

    if (tid < 16) ((float4*)bias_s)[tid] = ((const float4*)bias)[tid];

    // ---- e_s staging + max + transform ----
    float lmax = -1e30f;
#pragma unroll
    for (int r = 0; r < 4; r++) {
        float v = g_es[t * N + tid + r * 512];
        BB[tid + r * 512].x = v;
        lmax = fmaxf(lmax, v);
    }
    red[tid] = lmax;
    __syncthreads();
    for (int s = 256; s > 0; s >>= 1) {
        if (tid < s) red[tid] = fmaxf(red[tid], red[tid + s]);
        __syncthreads();
    }
    float esmax = red[0];
#pragma unroll
    for (int r = 0; r < 4; r++) {
        int j = tid + r * 512;
        float v = BB[j].x;
        BB[j] = make_float2(__expf(v - esmax), __expf(0.2f * (v - esmax)));
    }

    // ---- per-row constants ----
    int qd = lane >> 2;
    int il1 = wl * 16 + qd;
    int il2 = il1 + 8;
    int gi1 = i0 + il1, gi2 = i0 + il2;
    float ed1 = g_ed[t * N + gi1], ed2 = g_ed[t * N + gi2];
    float xm1 = ed1 + esmax, xm2 = ed2 + esmax;
    float M1 = fmaxf(xm1, 0.2f * xm1), M2 = fmaxf(xm2, 0.2f * xm2);
    float Ai1 = __expf(xm1 - M1), A2i1 = __expf(0.2f * xm1 - M1);
    float Ai2 = __expf(xm2 - M2), A2i2 = __expf(0.2f * xm2 - M2);

    float d[8][4];
#pragma unroll
    for (int nt = 0; nt < 8; nt++)
#pragma unroll
        for (int q = 0; q < 4; q++) d[nt][q] = 0.f;
    float sum1 = 0.f, sum2 = 0.f;

    int q = lane & 3;
    int c0j = 2 * q;
    uint32_t rowa = ((lane >> 4) << 3) + (lane & 7);
    uint32_t cola = ((lane >> 3) & 1) * 8;

    __syncthreads();   // BB ready

#pragma unroll 1
    for (int k = 0; k < 32; k++) {
        int j0 = k * 64;
        int bufk = k & 1;
        if (k < 31) { CP_WAIT1(); } else { CP_WAIT0(); }
        __syncthreads();   // chunk-k data visible

        const int* adjraw = (const int*)(sm + ADJ_OFF + bufk * ADJ_BYTES);
        uint32_t hhi_u = smb + HS_OFF + (uint32_t)bufk * 9216;
        int sl1 = gi1 - j0, sl2 = gi2 - j0;

#pragma unroll
        for (int ktl = 0; ktl < 2; ktl++) {
            int kt = kh * 2 + ktl;
            int jl = kt * 16 + c0j;

            float p1[4], p2[4];
#pragma unroll
            for (int dIdx = 0; dIdx < 4; dIdx++) {
                int dlt = (dIdx & 1) + (dIdx >> 1) * 8;
                int jj = jl + dlt;
                float2 bb = BB[j0 + jj];
                int v1 = adjraw[jj * ADJ_STRIDE + il1];
                int v2 = adjraw[jj * ADJ_STRIDE + il2];
                bool m1 = (v1 != 0) || (jj == sl1);
                bool m2 = (v2 != 0) || (jj == sl2);
                float pc1 = fmaxf(Ai1 * bb.x, A2i1 * bb.y);
                float pc2 = fmaxf(Ai2 * bb.x, A2i2 * bb.y);
                p1[dIdx] = m1 ? pc1 : 0.f;
                p2[dIdx] = m2 ? pc2 : 0.f;
            }
            sum1 += (p1[0] + p1[1]) + (p1[2] + p1[3]);
            sum2 += (p2[0] + p2[1]) + (p2[2] + p2[3]);

            uint32_t ap[4];
            ap[0] = pack_p(p1[0], p1[1]);
            ap[1] = pack_p(p2[0], p2[1]);
            ap[2] = pack_p(p1[2], p1[3]);
            ap[3] = pack_p(p2[2], p2[3]);

            uint32_t lcol = (uint32_t)(kt * 16) + cola;
#pragma unroll
            for (int cg = 0; cg < 4; cg++) {
                uint32_t roff = ((uint32_t)(cg * 16) + rowa) * 144 + lcol * 2;
                uint32_t h0, h1, h2, h3;
                ldsm4(h0, h1, h2, h3, hhi_u + roff);
                mma16816(d[cg * 2], ap, h0, h1);
                mma16816(d[cg * 2 + 1], ap, h2, h3);
            }
        }
        __syncthreads();   // buffer bufk fully consumed

        // ---- refill bufk with chunk k+2 ----
        if (k + 2 < 32) {
            int jn = j0 + 128;
#pragma unroll
            for (int r = 0; r < 4; r++) {
                int u = tid + r * 512;
                int j = u >> 5, off = u & 31;
                CP_ASYNC16(smb + ADJ_OFF + bufk * ADJ_BYTES + j * 528 + off * 16,
                           abase + (size_t)(jn + j) * N + off * 4);
            }
            int c = tid >> 3, o = tid & 7;
            uint32_t doff = (uint32_t)(c * 72 + o * 8) * 2;
            CP_ASYNC16(smb + HS_OFF + (uint32_t)bufk * 9216 + doff,
                       hhib + (size_t)c * N + jn + o * 8);
            CP_COMMIT();
        }
    }

    // ---- combine kt-halves ----
    sum1 += __shfl_xor_sync(0xffffffffu, sum1, 1);
    sum1 += __shfl_xor_sync(0xffffffffu, sum1, 2);
    sum2 += __shfl_xor_sync(0xffffffffu, sum2, 1);
    sum2 += __shfl_xor_sync(0xffffffffu, sum2, 2);

    __syncthreads();
    float* dc = (float*)(sm + DCOMB_OFF);
    float* sums_hi = (float*)(sm + RED_OFF);

    if (kh == 1) {
#pragma unroll
        for (int nt = 0; nt < 8; nt++)
            *(float4*)(dc + wl * 1024 + nt * 128 + lane * 4) =
                make_float4(d[nt][0], d[nt][1], d[nt][2], d[nt][3]);
        if ((lane & 3) == 0) {
            sums_hi[il1] = sum1;
            sums_hi[il2] = sum2;
        }
    }
    __syncthreads();

    if (kh == 0) {
        float st1 = sum1 + sums_hi[il1];
        float st2 = sum2 + sums_hi[il2];
        float s1 = 1.f / st1, s2 = 1.f / st2;

        float* o1 = g_out + ((size_t)t * N + gi1) * C;
        float* o2 = g_out + ((size_t)t * N + gi2) * C;
        int q2 = 2 * q;
#pragma unroll
        for (int nt = 0; nt < 8; nt++) {
            float4 pd = *(const float4*)(dc + wl * 1024 + nt * 128 + lane * 4);
            int c = nt * 8 + q2;
            *(float2*)(o1 + c) = make_float2((d[nt][0] + pd.x) * s1 + bias_s[c],
                                             (d[nt][1] + pd.y) * s1 + bias_s[c + 1]);
            *(float2*)(o2 + c) = make_float2((d[nt][2] + pd.z) * s2 + bias_s[c],
                                             (d[nt][3] + pd.w) * s2 + bias_s[c + 1]);
        }
    }
}

// ============================================================
// Kernel C (merged): inline cosine sims + temporal matvecs.
// ============================================================
__global__ __launch_bounds__(256) void kC(const float* __restrict__ t1w,
                                          const float* __restrict__ t2w,
                                          float* __restrict__ out) {
    __shared__ __align__(16) float w1[C * C];
    __shared__ __align__(16) float w2[C * C];
    __shared__ __align__(16) float2 us[32 * C];
    int tid = threadIdx.x;
    int t = blockIdx.y;
    int n0 = blockIdx.x * 32;

#pragma unroll
    for (int r = 0; r < 4; r++) {
        ((float4*)w1)[tid + r * 256] = ((const float4*)t1w)[tid + r * 256];
        ((float4*)w2)[tid + r * 256] = ((const float4*)t2w)[tid + r * 256];
    }

    int nl = tid >> 3;
    int dg = (tid & 7) * 8;
    int n = n0 + nl;
    size_t rowo = ((size_t)t * N + n) * C;

    float cur[8], prv[8], nxt[8];
#pragma unroll
    for (int qq = 0; qq < 2; qq++) {
        float4 v = *(const float4*)(g_out + rowo + dg + qq * 4);
        cur[qq * 4] = v.x; cur[qq * 4 + 1] = v.y;
        cur[qq * 4 + 2] = v.z; cur[qq * 4 + 3] = v.w;
    }
    if (t >= 1) {
#pragma unroll
        for (int qq = 0; qq < 2; qq++) {
            float4 v = *(const float4*)(g_out + rowo - (size_t)N * C + dg + qq * 4);
            prv[qq * 4] = v.x; prv[qq * 4 + 1] = v.y;
            prv[qq * 4 + 2] = v.z; prv[qq * 4 + 3] = v.w;
        }
    } else {
#pragma unroll
        for (int dd = 0; dd < 8; dd++) prv[dd] = 0.f;
    }
    if (t < T - 1) {
#pragma unroll
        for (int qq = 0; qq < 2; qq++) {
            float4 v = *(const float4*)(g_out + rowo + (size_t)N * C + dg + qq * 4);
            nxt[qq * 4] = v.x; nxt[qq * 4 + 1] = v.y;
            nxt[qq * 4 + 2] = v.z; nxt[qq * 4 + 3] = v.w;
        }
    } else {
#pragma unroll
        for (int dd = 0; dd < 8; dd++) nxt[dd] = 0.f;
    }

    float ab = 0.f, bc = 0.f, na = 0.f, nb = 0.f, nc = 0.f;
#pragma unroll
    for (int dd = 0; dd < 8; dd++) {
        ab = fmaf(prv[dd], cur[dd], ab);
        bc = fmaf(cur[dd], nxt[dd], bc);
        na = fmaf(prv[dd], prv[dd], na);
        nb = fmaf(cur[dd], cur[dd], nb);
        nc = fmaf(nxt[dd], nxt[dd], nc);
    }
#pragma unroll
    for (int off = 1; off < 8; off <<= 1) {
        ab += __shfl_xor_sync(0xffffffffu, ab, off);
        bc += __shfl_xor_sync(0xffffffffu, bc, off);
        na += __shfl_xor_sync(0xffffffffu, na, off);
        nb += __shfl_xor_sync(0xffffffffu, nb, off);
        nc += __shfl_xor_sync(0xffffffffu, nc, off);
    }
    float rb = fmaxf(sqrtf(nb), 1e-8f);
    float tem_prev = ab / (fmaxf(sqrtf(na), 1e-8f) * rb);
    float tem_next = bc / (rb * fmaxf(sqrtf(nc), 1e-8f));

    float2* urow = us + nl * C + dg;
#pragma unroll
    for (int dd = 0; dd < 8; dd++)
        urow[dd] = make_float2(tem_next * nxt[dd], tem_prev * prv[dd]);
    __syncthreads();

    unsigned long long acc[4];
#pragma unroll
    for (int qq = 0; qq < 4; qq++)
        acc[qq] = pk2(cur[qq * 2], cur[qq * 2 + 1]);

    const float2* un = us + nl * C;
#pragma unroll 8
    for (int c = 0; c < C; c++) {
        float2 u = un[c];
        unsigned long long u1 = pk2(u.x, u.x);
        unsigned long long u2 = pk2(u.y, u.y);
        const ulonglong2* r1 = (const ulonglong2*)(w1 + c * C + dg);
        const ulonglong2* r2 = (const ulonglong2*)(w2 + c * C + dg);
        ulonglong2 wv1 = r1[0], wv1b = r1[1];
        ulonglong2 wv2 = r2[0], wv2b = r2[1];
        fma2(acc[0], wv1.x, u1);
        fma2(acc[1], wv1.y, u1);
        fma2(acc[2], wv1b.x, u1);
        fma2(acc[3], wv1b.y, u1);
        fma2(acc[0], wv2.x, u2);
        fma2(acc[1], wv2.y, u2);
        fma2(acc[2], wv2b.x, u2);
        fma2(acc[3], wv2b.y, u2);
    }

    float r[8];
#pragma unroll
    for (int qq = 0; qq < 4; qq++) upk2(acc[qq], r[qq * 2], r[qq * 2 + 1]);
#pragma unroll
    for (int qq = 0; qq < 2; qq++) {
        *(float4*)(out + rowo + dg + qq * 4) =
            make_float4(r[qq * 4], r[qq * 4 + 1], r[qq * 4 + 2], r[qq * 4 + 3]);
    }
}

// ============================================================
extern "C" void kernel_launch(void* const* d_in, const int* in_sizes, int n_in,
                              void* d_out, int out_size) {
    const float* x = (const float*)d_in[0];
    const int* adj = (const int*)d_in[1];
    const float* W = (const float*)d_in[2];
    const float* asrc = (const float*)d_in[3];
    const float* adst = (const float*)d_in[4];
    const float* bias = (const float*)d_in[5];
    const float* t1w = (const float*)d_in[6];
    const float* t2w = (const float*)d_in[7];
    float* out = (float*)d_out;

    cudaFuncSetAttribute(kA, cudaFuncAttributeMaxDynamicSharedMemorySize, KA_SMEM);
    cudaFuncSetAttribute(kB, cudaFuncAttributeMaxDynamicSharedMemorySize, KB_SMEM);

    kA<<<dim3(N / 64, T), 128, KA_SMEM>>>(x, W, asrc, adst);
    kB<<<dim3(N / 128, T), 512, KB_SMEM>>>(adj, bias);
    kC<<<dim3(N / 32, T), 256>>>(t1w, t2w, out);
}

// round 12
// speedup vs baseline: 2.7658x; 1.0210x over previous
#include <cuda_runtime.h>
#include <cuda_fp16.h>
#include <math.h>
#include <stdint.h>

#define T 8
#define N 2048
#define F 128
#define C 64

// ---------------- device scratch ----------------
__device__ float g_es[T * N];
__device__ float g_ed[T * N];
__device__ float g_out[T * N * C];
__device__ __half g_hThi[T * C * N];   // h transposed fp16: [t][c][n]
__device__ __half g_Whi[C * F];        // W^T hi fp16: [c][k]
__device__ __half g_Wlo[C * F];        // W^T lo fp16

// ---------------- helpers ----------------
__device__ __forceinline__ uint32_t smem_u32(const void* p) {
    uint32_t a;
    asm("{ .reg .u64 t; cvta.to.shared.u64 t, %1; cvt.u32.u64 %0, t; }"
        : "=r"(a) : "l"(p));
    return a;
}
#define CP_ASYNC16(dst, src) \
    asm volatile("cp.async.cg.shared.global [%0], [%1], 16;" :: "r"(dst), "l"(src) : "memory")
#define CP_COMMIT() asm volatile("cp.async.commit_group;" ::: "memory")
#define CP_WAIT0() asm volatile("cp.async.wait_group 0;" ::: "memory")
#define CP_WAIT1() asm volatile("cp.async.wait_group 1;" ::: "memory")

__device__ __forceinline__ void ldsm4(uint32_t& r0, uint32_t& r1, uint32_t& r2,
                                      uint32_t& r3, uint32_t addr) {
    asm volatile("ldmatrix.sync.aligned.m8n8.x4.shared.b16 {%0,%1,%2,%3}, [%4];"
                 : "=r"(r0), "=r"(r1), "=r"(r2), "=r"(r3) : "r"(addr));
}
__device__ __forceinline__ void mma16816(float* d, const uint32_t* a, uint32_t b0,
                                         uint32_t b1) {
    asm volatile(
        "mma.sync.aligned.m16n8k16.row.col.f32.f16.f16.f32 "
        "{%0,%1,%2,%3}, {%4,%5,%6,%7}, {%8,%9}, {%0,%1,%2,%3};"
        : "+f"(d[0]), "+f"(d[1]), "+f"(d[2]), "+f"(d[3])
        : "r"(a[0]), "r"(a[1]), "r"(a[2]), "r"(a[3]), "r"(b0), "r"(b1));
}
__device__ __forceinline__ uint32_t pack_p(float p0, float p1) {
    __half2 h = __floats2half2_rn(p0, p1);
    return *(uint32_t*)&h;
}

// ---------------- f32x2 helpers ----------------
__device__ __forceinline__ unsigned long long pk2(float lo, float hi) {
    unsigned long long r;
    asm("mov.b64 %0, {%1, %2};" : "=l"(r) : "f"(lo), "f"(hi));
    return r;
}
__device__ __forceinline__ void upk2(unsigned long long v, float& lo, float& hi) {
    asm("mov.b64 {%0, %1}, %2;" : "=f"(lo), "=f"(hi) : "l"(v));
}
__device__ __forceinline__ void fma2(unsigned long long& d, unsigned long long a,
                                     unsigned long long b) {
    asm("fma.rn.f32x2 %0, %1, %2, %0;" : "+l"(d) : "l"(a), "l"(b));
}

// ============================================================
// Kernel W: one-time W -> transposed hi/lo fp16 (global)
// ============================================================
__global__ __launch_bounds__(256) void kW(const float* __restrict__ W) {
#pragma unroll
    for (int i = 0; i < 32; i++) {
        int e = threadIdx.x + i * 256;
        int k = e >> 6, c = e & 63;
        float v = W[e];
        __half h = __float2half_rn(v);
        g_Whi[c * F + k] = h;
        g_Wlo[c * F + k] = __float2half_rn(v - __half2float(h));
    }
}

// ============================================================
// Kernel A (HMMA): h = x @ W via split-fp16 (3 products).
// CTA: 128 thr (4 warps), 64 rows. W hi/lo pre-converted.
// ============================================================
#define KA_WHI  0            // 64 x 136 fp16 = 17408
#define KA_WLO  17408
#define KA_XHI  34816
#define KA_XLO  52224
#define KA_HHI  KA_XHI       // overlay after MMA
#define KA_SMEM 69632

__global__ __launch_bounds__(128) void kA(const float* __restrict__ x,
                                          const float* __restrict__ asrc,
                                          const float* __restrict__ adst) {
    extern __shared__ __align__(16) char smA[];
    __half* xh = (__half*)(smA + KA_XHI);
    __half* xl = (__half*)(smA + KA_XLO);
    uint32_t smb = smem_u32(smA);

    int tid = threadIdx.x;
    int lane = tid & 31;
    int w = tid >> 5;
    int t = blockIdx.y;
    int n0 = blockIdx.x * 64;

    // ---- cp.async W hi/lo tiles (overlaps with x load) ----
    // 64 rows x 128 k halves = 1024 chunks of 16B per array; 16 chunks/row.
#pragma unroll
    for (int r = 0; r < 8; r++) {
        int u = tid + r * 128;
        int c = u >> 4, seg = u & 15;
        uint32_t doff = (uint32_t)(c * 136 + seg * 8) * 2;
        CP_ASYNC16(smb + KA_WHI + doff, g_Whi + c * F + seg * 8);
        CP_ASYNC16(smb + KA_WLO + doff, g_Wlo + c * F + seg * 8);
    }
    CP_COMMIT();

    // ---- load + convert x -> [row][k] hi/lo, stride 136 ----
    {
        int row = tid >> 1, half = tid & 1;
        const float4* xr4 =
            (const float4*)(x + ((size_t)t * N + n0 + row) * F + half * 64);
        __half* xhp = xh + row * 136 + half * 64;
        __half* xlp = xl + row * 136 + half * 64;
#pragma unroll
        for (int j = 0; j < 16; j++) {
            float4 v = xr4[j];
            __half2 h01 = __floats2half2_rn(v.x, v.y);
            __half2 h23 = __floats2half2_rn(v.z, v.w);
            float2 f01 = __half22float2(h01);
            float2 f23 = __half22float2(h23);
            __half2 l01 = __floats2half2_rn(v.x - f01.x, v.y - f01.y);
            __half2 l23 = __floats2half2_rn(v.z - f23.x, v.w - f23.y);
            *(uint32_t*)(xhp + j * 4) = *(uint32_t*)&h01;
            *(uint32_t*)(xhp + j * 4 + 2) = *(uint32_t*)&h23;
            *(uint32_t*)(xlp + j * 4) = *(uint32_t*)&l01;
            *(uint32_t*)(xlp + j * 4 + 2) = *(uint32_t*)&l23;
        }
    }
    CP_WAIT0();
    __syncthreads();

    // ---- MMA: 16 rows per warp, 3 split products ----
    float d[8][4];
#pragma unroll
    for (int nt = 0; nt < 8; nt++)
#pragma unroll
        for (int q = 0; q < 4; q++) d[nt][q] = 0.f;

    uint32_t xhi_b = smb + KA_XHI;
    uint32_t xlo_b = smb + KA_XLO;
    uint32_t whi_b = smb + KA_WHI;
    uint32_t wlo_b = smb + KA_WLO;
    int r0 = w * 16;
    uint32_t rowOffA = (lane & 7) + ((lane >> 3) & 1) * 8;
    uint32_t colOffA = (lane >> 4) * 8;
    uint32_t rowB = ((lane >> 4) << 3) + (lane & 7);
    uint32_t colB = ((lane >> 3) & 1) * 8;

#pragma unroll
    for (int ks = 0; ks < 8; ks++) {
        uint32_t kb = ks * 16;
        uint32_t aoff = ((r0 + rowOffA) * 136 + kb + colOffA) * 2;
        uint32_t ahi[4], alo[4];
        ldsm4(ahi[0], ahi[1], ahi[2], ahi[3], xhi_b + aoff);
        ldsm4(alo[0], alo[1], alo[2], alo[3], xlo_b + aoff);
#pragma unroll
        for (int cg = 0; cg < 4; cg++) {
            uint32_t boff = ((cg * 16 + rowB) * 136 + kb + colB) * 2;
            uint32_t h0, h1, h2, h3, l0, l1, l2, l3;
            ldsm4(h0, h1, h2, h3, whi_b + boff);
            ldsm4(l0, l1, l2, l3, wlo_b + boff);
            mma16816(d[cg * 2], ahi, h0, h1);
            mma16816(d[cg * 2], ahi, l0, l1);
            mma16816(d[cg * 2], alo, h0, h1);
            mma16816(d[cg * 2 + 1], ahi, h2, h3);
            mma16816(d[cg * 2 + 1], ahi, l2, l3);
            mma16816(d[cg * 2 + 1], alo, h2, h3);
        }
    }

    // ---- es/ed from f32 frags ----
    int r1 = r0 + (lane >> 2), r2 = r1 + 8;
    float es1 = 0.f, ed1 = 0.f, es2 = 0.f, ed2 = 0.f;
#pragma unroll
    for (int nt = 0; nt < 8; nt++) {
        int c = nt * 8 + 2 * (lane & 3);
        float a0 = asrc[c], a1 = asrc[c + 1];
        float b0 = adst[c], b1 = adst[c + 1];
        es1 += d[nt][0] * a0 + d[nt][1] * a1;
        ed1 += d[nt][0] * b0 + d[nt][1] * b1;
        es2 += d[nt][2] * a0 + d[nt][3] * a1;
        ed2 += d[nt][2] * b0 + d[nt][3] * b1;
    }
#pragma unroll
    for (int off = 1; off < 4; off <<= 1) {
        es1 += __shfl_xor_sync(0xffffffffu, es1, off);
        ed1 += __shfl_xor_sync(0xffffffffu, ed1, off);
        es2 += __shfl_xor_sync(0xffffffffu, es2, off);
        ed2 += __shfl_xor_sync(0xffffffffu, ed2, off);
    }
    if ((lane & 3) == 0) {
        g_es[t * N + n0 + r1] = es1;
        g_ed[t * N + n0 + r1] = ed1;
        g_es[t * N + n0 + r2] = es2;
        g_ed[t * N + n0 + r2] = ed2;
    }

    // ---- h (hi only) transpose into smem, overlay x region ----
    __syncthreads();
    __half* hh = (__half*)(smA + KA_HHI);
#pragma unroll
    for (int nt = 0; nt < 8; nt++) {
        int c = nt * 8 + 2 * (lane & 3);
        hh[c * 136 + r1] = __float2half_rn(d[nt][0]);
        hh[(c + 1) * 136 + r1] = __float2half_rn(d[nt][1]);
        hh[c * 136 + r2] = __float2half_rn(d[nt][2]);
        hh[(c + 1) * 136 + r2] = __float2half_rn(d[nt][3]);
    }
    __syncthreads();

    // ---- coalesced writeout ----
    __half* dhi = g_hThi + (size_t)t * C * N;
#pragma unroll
    for (int i = 0; i < 4; i++) {
        int u = tid + i * 128;
        int c = u >> 3, seg = u & 7;
        *(uint4*)(dhi + (size_t)c * N + n0 + seg * 8) = *(uint4*)(hh + c * 136 + seg * 8);
    }
}

// ============================================================
// Kernel B: masked-softmax aggregation via fp16 HMMA.
// 512 threads, kt-split warp pairs; 3-deep buffers, ONE sync/chunk.
// ============================================================
#define ADJ_STRIDE 132
#define ADJ_BYTES  33792
#define BB_OFF   0                     // 16384
#define HS_OFF   16384                 // 3 x 9216 = 27648
#define ADJ_OFF  44032                 // 3 x 33792 = 101376
#define RED_OFF  145408                // 2048
#define BIAS_OFF 147456                // 256
#define KB_SMEM  147712
#define DCOMB_OFF ADJ_OFF

__global__ __launch_bounds__(512) void kB(const int* __restrict__ adj,
                                          const float* __restrict__ bias) {
    extern __shared__ __align__(16) char sm[];
    float2* BB = (float2*)(sm + BB_OFF);
    float* red = (float*)(sm + RED_OFF);
    float* bias_s = (float*)(sm + BIAS_OFF);
    uint32_t smb = smem_u32(sm);

    int tid = threadIdx.x;
    int wid = tid >> 5;
    int lane = tid & 31;
    int wl = wid & 7;
    int kh = wid >> 3;
    int t = blockIdx.y;
    int i0 = blockIdx.x * 128;

    const int* abase = adj + (size_t)t * N * N + i0;
    const __half* hhib = g_hThi + (size_t)t * C * N;

    // ---- prologue: chunks 0 and 1 into bufs 0,1 ----
#pragma unroll
    for (int b = 0; b < 2; b++) {
#pragma unroll
        for (int r = 0; r < 4; r++) {
            int u = tid + r * 512;
            int j = u >> 5, off = u & 31;
            CP_ASYNC16(smb + ADJ_OFF + b * ADJ_BYTES + j * 528 + off * 16,
                       abase + (size_t)(b * 64 + j) * N + off * 4);
        }
        int c = tid >> 3, o = tid & 7;
        uint32_t doff = (uint32_t)(c * 72 + o * 8) * 2;
        CP_ASYNC16(smb + HS_OFF + b * 9216 + doff, hhib + (size_t)c * N + b * 64 + o * 8);
        CP_COMMIT();
    }

    if (tid < 16) ((float4*)bias_s)[tid] = ((const float4*)bias)[tid];

    // ---- e_s staging + max + transform ----
    float lmax = -1e30f;
#pragma unroll
    for (int r = 0; r < 4; r++) {
        float v = g_es[t * N + tid + r * 512];
        BB[tid + r * 512].x = v;
        lmax = fmaxf(lmax, v);
    }
    red[tid] = lmax;
    __syncthreads();
    for (int s = 256; s > 0; s >>= 1) {
        if (tid < s) red[tid] = fmaxf(red[tid], red[tid + s]);
        __syncthreads();
    }
    float esmax = red[0];
#pragma unroll
    for (int r = 0; r < 4; r++) {
        int j = tid + r * 512;
        float v = BB[j].x;
        BB[j] = make_float2(__expf(v - esmax), __expf(0.2f * (v - esmax)));
    }

    // ---- per-row constants ----
    int qd = lane >> 2;
    int il1 = wl * 16 + qd;
    int il2 = il1 + 8;
    int gi1 = i0 + il1, gi2 = i0 + il2;
    float ed1 = g_ed[t * N + gi1], ed2 = g_ed[t * N + gi2];
    float xm1 = ed1 + esmax, xm2 = ed2 + esmax;
    float M1 = fmaxf(xm1, 0.2f * xm1), M2 = fmaxf(xm2, 0.2f * xm2);
    float Ai1 = __expf(xm1 - M1), A2i1 = __expf(0.2f * xm1 - M1);
    float Ai2 = __expf(xm2 - M2), A2i2 = __expf(0.2f * xm2 - M2);

    float d[8][4];
#pragma unroll
    for (int nt = 0; nt < 8; nt++)
#pragma unroll
        for (int q = 0; q < 4; q++) d[nt][q] = 0.f;
    float sum1 = 0.f, sum2 = 0.f;

    int q = lane & 3;
    int c0j = 2 * q;
    uint32_t rowa = ((lane >> 4) << 3) + (lane & 7);
    uint32_t cola = ((lane >> 3) & 1) * 8;

    __syncthreads();   // BB ready

#pragma unroll 1
    for (int k = 0; k < 32; k++) {
        int j0 = k * 64;
        int bufk = k % 3;
        if (k < 31) { CP_WAIT1(); } else { CP_WAIT0(); }
        __syncthreads();   // chunk-k data visible; all prior compute done

        // ---- refill buf (k+2)%3 with chunk k+2 (read last at iter k-1) ----
        if (k + 2 < 32) {
            int bufn = (k + 2) % 3;
            int jn = j0 + 128;
#pragma unroll
            for (int r = 0; r < 4; r++) {
                int u = tid + r * 512;
                int j = u >> 5, off = u & 31;
                CP_ASYNC16(smb + ADJ_OFF + bufn * ADJ_BYTES + j * 528 + off * 16,
                           abase + (size_t)(jn + j) * N + off * 4);
            }
            int c = tid >> 3, o = tid & 7;
            uint32_t doff = (uint32_t)(c * 72 + o * 8) * 2;
            CP_ASYNC16(smb + HS_OFF + (uint32_t)bufn * 9216 + doff,
                       hhib + (size_t)c * N + jn + o * 8);
            CP_COMMIT();
        }

        const int* adjraw = (const int*)(sm + ADJ_OFF + bufk * ADJ_BYTES);
        uint32_t hhi_u = smb + HS_OFF + (uint32_t)bufk * 9216;
        int sl1 = gi1 - j0, sl2 = gi2 - j0;

#pragma unroll
        for (int ktl = 0; ktl < 2; ktl++) {
            int kt = kh * 2 + ktl;
            int jl = kt * 16 + c0j;

            float p1[4], p2[4];
#pragma unroll
            for (int dIdx = 0; dIdx < 4; dIdx++) {
                int dlt = (dIdx & 1) + (dIdx >> 1) * 8;
                int jj = jl + dlt;
                float2 bb = BB[j0 + jj];
                int v1 = adjraw[jj * ADJ_STRIDE + il1];
                int v2 = adjraw[jj * ADJ_STRIDE + il2];
                bool m1 = (v1 != 0) || (jj == sl1);
                bool m2 = (v2 != 0) || (jj == sl2);
                float pc1 = fmaxf(Ai1 * bb.x, A2i1 * bb.y);
                float pc2 = fmaxf(Ai2 * bb.x, A2i2 * bb.y);
                p1[dIdx] = m1 ? pc1 : 0.f;
                p2[dIdx] = m2 ? pc2 : 0.f;
            }
            sum1 += (p1[0] + p1[1]) + (p1[2] + p1[3]);
            sum2 += (p2[0] + p2[1]) + (p2[2] + p2[3]);

            uint32_t ap[4];
            ap[0] = pack_p(p1[0], p1[1]);
            ap[1] = pack_p(p2[0], p2[1]);
            ap[2] = pack_p(p1[2], p1[3]);
            ap[3] = pack_p(p2[2], p2[3]);

            uint32_t lcol = (uint32_t)(kt * 16) + cola;
#pragma unroll
            for (int cg = 0; cg < 4; cg++) {
                uint32_t roff = ((uint32_t)(cg * 16) + rowa) * 144 + lcol * 2;
                uint32_t h0, h1, h2, h3;
                ldsm4(h0, h1, h2, h3, hhi_u + roff);
                mma16816(d[cg * 2], ap, h0, h1);
                mma16816(d[cg * 2 + 1], ap, h2, h3);
            }
        }
    }

    // ---- combine kt-halves ----
    sum1 += __shfl_xor_sync(0xffffffffu, sum1, 1);
    sum1 += __shfl_xor_sync(0xffffffffu, sum1, 2);
    sum2 += __shfl_xor_sync(0xffffffffu, sum2, 1);
    sum2 += __shfl_xor_sync(0xffffffffu, sum2, 2);

    __syncthreads();
    float* dc = (float*)(sm + DCOMB_OFF);
    float* sums_hi = (float*)(sm + RED_OFF);

    if (kh == 1) {
#pragma unroll
        for (int nt = 0; nt < 8; nt++)
            *(float4*)(dc + wl * 1024 + nt * 128 + lane * 4) =
                make_float4(d[nt][0], d[nt][1], d[nt][2], d[nt][3]);
        if ((lane & 3) == 0) {
            sums_hi[il1] = sum1;
            sums_hi[il2] = sum2;
        }
    }
    __syncthreads();

    if (kh == 0) {
        float st1 = sum1 + sums_hi[il1];
        float st2 = sum2 + sums_hi[il2];
        float s1 = 1.f / st1, s2 = 1.f / st2;

        float* o1 = g_out + ((size_t)t * N + gi1) * C;
        float* o2 = g_out + ((size_t)t * N + gi2) * C;
        int q2 = 2 * q;
#pragma unroll
        for (int nt = 0; nt < 8; nt++) {
            float4 pd = *(const float4*)(dc + wl * 1024 + nt * 128 + lane * 4);
            int c = nt * 8 + q2;
            *(float2*)(o1 + c) = make_float2((d[nt][0] + pd.x) * s1 + bias_s[c],
                                             (d[nt][1] + pd.y) * s1 + bias_s[c + 1]);
            *(float2*)(o2 + c) = make_float2((d[nt][2] + pd.z) * s2 + bias_s[c],
                                             (d[nt][3] + pd.w) * s2 + bias_s[c + 1]);
        }
    }
}

// ============================================================
// Kernel C: inline cosine sims + temporal matvecs.
// 64 nodes/CTA, 2 nodes per thread (shared weight reads).
// us padded stride 66 (conflict-free).
// ============================================================
#define KC_W1 0            // 16384
#define KC_W2 16384        // 16384
#define KC_US 32768        // 64 x 66 float2 = 33792
#define KC_SMEM 66560

__global__ __launch_bounds__(256) void kC(const float* __restrict__ t1w,
                                          const float* __restrict__ t2w,
                                          float* __restrict__ out) {
    extern __shared__ __align__(16) char smC[];
    float* w1 = (float*)(smC + KC_W1);
    float* w2 = (float*)(smC + KC_W2);
    float2* us = (float2*)(smC + KC_US);

    int tid = threadIdx.x;
    int t = blockIdx.y;
    int n0 = blockIdx.x * 64;

#pragma unroll
    for (int r = 0; r < 4; r++) {
        ((float4*)w1)[tid + r * 256] = ((const float4*)t1w)[tid + r * 256];
        ((float4*)w2)[tid + r * 256] = ((const float4*)t2w)[tid + r * 256];
    }

    int nl = tid >> 3;
    int dg = (tid & 7) * 8;

    float curA[8], curB[8];
    unsigned long long accA[4], accB[4];

#pragma unroll
    for (int half = 0; half < 2; half++) {
        int node = nl + half * 32;
        size_t rowo = ((size_t)t * N + n0 + node) * C;
        float cur[8], prv[8], nxt[8];
#pragma unroll
        for (int qq = 0; qq < 2; qq++) {
            float4 v = *(const float4*)(g_out + rowo + dg + qq * 4);
            cur[qq * 4] = v.x; cur[qq * 4 + 1] = v.y;
            cur[qq * 4 + 2] = v.z; cur[qq * 4 + 3] = v.w;
        }
        if (t >= 1) {
#pragma unroll
            for (int qq = 0; qq < 2; qq++) {
                float4 v = *(const float4*)(g_out + rowo - (size_t)N * C + dg + qq * 4);
                prv[qq * 4] = v.x; prv[qq * 4 + 1] = v.y;
                prv[qq * 4 + 2] = v.z; prv[qq * 4 + 3] = v.w;
            }
        } else {
#pragma unroll
            for (int dd = 0; dd < 8; dd++) prv[dd] = 0.f;
        }
        if (t < T - 1) {
#pragma unroll
            for (int qq = 0; qq < 2; qq++) {
                float4 v = *(const float4*)(g_out + rowo + (size_t)N * C + dg + qq * 4);
                nxt[qq * 4] = v.x; nxt[qq * 4 + 1] = v.y;
                nxt[qq * 4 + 2] = v.z; nxt[qq * 4 + 3] = v.w;
            }
        } else {
#pragma unroll
            for (int dd = 0; dd < 8; dd++) nxt[dd] = 0.f;
        }

        float ab = 0.f, bc = 0.f, na = 0.f, nb = 0.f, nc = 0.f;
#pragma unroll
        for (int dd = 0; dd < 8; dd++) {
            ab = fmaf(prv[dd], cur[dd], ab);
            bc = fmaf(cur[dd], nxt[dd], bc);
            na = fmaf(prv[dd], prv[dd], na);
            nb = fmaf(cur[dd], cur[dd], nb);
            nc = fmaf(nxt[dd], nxt[dd], nc);
        }
#pragma unroll
        for (int off = 1; off < 8; off <<= 1) {
            ab += __shfl_xor_sync(0xffffffffu, ab, off);
            bc += __shfl_xor_sync(0xffffffffu, bc, off);
            na += __shfl_xor_sync(0xffffffffu, na, off);
            nb += __shfl_xor_sync(0xffffffffu, nb, off);
            nc += __shfl_xor_sync(0xffffffffu, nc, off);
        }
        float rb = fmaxf(sqrtf(nb), 1e-8f);
        float tem_prev = ab / (fmaxf(sqrtf(na), 1e-8f) * rb);
        float tem_next = bc / (rb * fmaxf(sqrtf(nc), 1e-8f));

        float2* urow = us + node * 66 + dg;
#pragma unroll
        for (int dd = 0; dd < 8; dd++)
            urow[dd] = make_float2(tem_next * nxt[dd], tem_prev * prv[dd]);

        if (half == 0) {
#pragma unroll
            for (int dd = 0; dd < 8; dd++) curA[dd] = cur[dd];
        } else {
#pragma unroll
            for (int dd = 0; dd < 8; dd++) curB[dd] = cur[dd];
        }
    }
    __syncthreads();

#pragma unroll
    for (int qq = 0; qq < 4; qq++) {
        accA[qq] = pk2(curA[qq * 2], curA[qq * 2 + 1]);
        accB[qq] = pk2(curB[qq * 2], curB[qq * 2 + 1]);
    }

    const float2* unA = us + nl * 66;
    const float2* unB = us + (nl + 32) * 66;
#pragma unroll 4
    for (int c = 0; c < C; c++) {
        float2 uA = unA[c];
        float2 uB = unB[c];
        unsigned long long u1A = pk2(uA.x, uA.x);
        unsigned long long u2A = pk2(uA.y, uA.y);
        unsigned long long u1B = pk2(uB.x, uB.x);
        unsigned long long u2B = pk2(uB.y, uB.y);
        const ulonglong2* r1 = (const ulonglong2*)(w1 + c * C + dg);
        const ulonglong2* r2 = (const ulonglong2*)(w2 + c * C + dg);
        ulonglong2 wv1 = r1[0], wv1b = r1[1];
        ulonglong2 wv2 = r2[0], wv2b = r2[1];
        fma2(accA[0], wv1.x, u1A);
        fma2(accA[1], wv1.y, u1A);
        fma2(accA[2], wv1b.x, u1A);
        fma2(accA[3], wv1b.y, u1A);
        fma2(accA[0], wv2.x, u2A);
        fma2(accA[1], wv2.y, u2A);
        fma2(accA[2], wv2b.x, u2A);
        fma2(accA[3], wv2b.y, u2A);
        fma2(accB[0], wv1.x, u1B);
        fma2(accB[1], wv1.y, u1B);
        fma2(accB[2], wv1b.x, u1B);
        fma2(accB[3], wv1b.y, u1B);
        fma2(accB[0], wv2.x, u2B);
        fma2(accB[1], wv2.y, u2B);
        fma2(accB[2], wv2b.x, u2B);
        fma2(accB[3], wv2b.y, u2B);
    }

    float rA[8], rB[8];
#pragma unroll
    for (int qq = 0; qq < 4; qq++) {
        upk2(accA[qq], rA[qq * 2], rA[qq * 2 + 1]);
        upk2(accB[qq], rB[qq * 2], rB[qq * 2 + 1]);
    }
    size_t rowA = ((size_t)t * N + n0 + nl) * C;
    size_t rowB = ((size_t)t * N + n0 + nl + 32) * C;
#pragma unroll
    for (int qq = 0; qq < 2; qq++) {
        *(float4*)(out + rowA + dg + qq * 4) =
            make_float4(rA[qq * 4], rA[qq * 4 + 1], rA[qq * 4 + 2], rA[qq * 4 + 3]);
        *(float4*)(out + rowB + dg + qq * 4) =
            make_float4(rB[qq * 4], rB[qq * 4 + 1], rB[qq * 4 + 2], rB[qq * 4 + 3]);
    }
}

// ============================================================
extern "C" void kernel_launch(void* const* d_in, const int* in_sizes, int n_in,
                              void* d_out, int out_size) {
    const float* x = (const float*)d_in[0];
    const int* adj = (const int*)d_in[1];
    const float* W = (const float*)d_in[2];
    const float* asrc = (const float*)d_in[3];
    const float* adst = (const float*)d_in[4];
    const float* bias = (const float*)d_in[5];
    const float* t1w = (const float*)d_in[6];
    const float* t2w = (const float*)d_in[7];
    float* out = (float*)d_out;

    cudaFuncSetAttribute(kA, cudaFuncAttributeMaxDynamicSharedMemorySize, KA_SMEM);
    cudaFuncSetAttribute(kB, cudaFuncAttributeMaxDynamicSharedMemorySize, KB_SMEM);
    cudaFuncSetAttribute(kC, cudaFuncAttributeMaxDynamicSharedMemorySize, KC_SMEM);

    kW<<<1, 256>>>(W);
    kA<<<dim3(N / 64, T), 128, KA_SMEM>>>(x, asrc, adst);
    kB<<<dim3(N / 128, T), 512, KB_SMEM>>>(adj, bias);
    kC<<<dim3(N / 64, T), 256, KC_SMEM>>>(t1w, t2w, out);
}

// round 13
// speedup vs baseline: 3.0233x; 1.0931x over previous
#include <cuda_runtime.h>
#include <cuda_fp16.h>
#include <math.h>
#include <stdint.h>

#define T 8
#define N 2048
#define F 128
#define C 64

// ---------------- device scratch ----------------
__device__ float g_es[T * N];
__device__ float g_ed[T * N];
__device__ float g_out[T * N * C];
__device__ __half g_hThi[T * C * N];   // h transposed fp16: [t][c][n]
__device__ __half g_Whi[C * F];        // W^T hi fp16: [c][k]
__device__ __half g_Wlo[C * F];        // W^T lo fp16

// ---------------- helpers ----------------
__device__ __forceinline__ uint32_t smem_u32(const void* p) {
    uint32_t a;
    asm("{ .reg .u64 t; cvta.to.shared.u64 t, %1; cvt.u32.u64 %0, t; }"
        : "=r"(a) : "l"(p));
    return a;
}
#define CP_ASYNC16(dst, src) \
    asm volatile("cp.async.cg.shared.global [%0], [%1], 16;" :: "r"(dst), "l"(src) : "memory")
#define CP_COMMIT() asm volatile("cp.async.commit_group;" ::: "memory")
#define CP_WAIT0() asm volatile("cp.async.wait_group 0;" ::: "memory")
#define CP_WAIT1() asm volatile("cp.async.wait_group 1;" ::: "memory")

__device__ __forceinline__ void ldsm4(uint32_t& r0, uint32_t& r1, uint32_t& r2,
                                      uint32_t& r3, uint32_t addr) {
    asm volatile("ldmatrix.sync.aligned.m8n8.x4.shared.b16 {%0,%1,%2,%3}, [%4];"
                 : "=r"(r0), "=r"(r1), "=r"(r2), "=r"(r3) : "r"(addr));
}
__device__ __forceinline__ void mma16816(float* d, const uint32_t* a, uint32_t b0,
                                         uint32_t b1) {
    asm volatile(
        "mma.sync.aligned.m16n8k16.row.col.f32.f16.f16.f32 "
        "{%0,%1,%2,%3}, {%4,%5,%6,%7}, {%8,%9}, {%0,%1,%2,%3};"
        : "+f"(d[0]), "+f"(d[1]), "+f"(d[2]), "+f"(d[3])
        : "r"(a[0]), "r"(a[1]), "r"(a[2]), "r"(a[3]), "r"(b0), "r"(b1));
}
__device__ __forceinline__ uint32_t pack_p(float p0, float p1) {
    __half2 h = __floats2half2_rn(p0, p1);
    return *(uint32_t*)&h;
}

// ---------------- f32x2 helpers ----------------
__device__ __forceinline__ unsigned long long pk2(float lo, float hi) {
    unsigned long long r;
    asm("mov.b64 %0, {%1, %2};" : "=l"(r) : "f"(lo), "f"(hi));
    return r;
}
__device__ __forceinline__ void upk2(unsigned long long v, float& lo, float& hi) {
    asm("mov.b64 {%0, %1}, %2;" : "=f"(lo), "=f"(hi) : "l"(v));
}
__device__ __forceinline__ void fma2(unsigned long long& d, unsigned long long a,
                                     unsigned long long b) {
    asm("fma.rn.f32x2 %0, %1, %2, %0;" : "+l"(d) : "l"(a), "l"(b));
}

// ============================================================
// Kernel W: one-time W -> transposed hi/lo fp16 (global)
// ============================================================
__global__ __launch_bounds__(256) void kW(const float* __restrict__ W) {
#pragma unroll
    for (int i = 0; i < 32; i++) {
        int e = threadIdx.x + i * 256;
        int k = e >> 6, c = e & 63;
        float v = W[e];
        __half h = __float2half_rn(v);
        g_Whi[c * F + k] = h;
        g_Wlo[c * F + k] = __float2half_rn(v - __half2float(h));
    }
}

// ============================================================
// Kernel A (HMMA): h = x @ W via split-fp16 (3 products).
// CTA: 128 thr (4 warps), 64 rows. W hi/lo pre-converted.
// ============================================================
#define KA_WHI  0            // 64 x 136 fp16 = 17408
#define KA_WLO  17408
#define KA_XHI  34816
#define KA_XLO  52224
#define KA_HHI  KA_XHI       // overlay after MMA
#define KA_SMEM 69632

__global__ __launch_bounds__(128) void kA(const float* __restrict__ x,
                                          const float* __restrict__ asrc,
                                          const float* __restrict__ adst) {
    extern __shared__ __align__(16) char smA[];
    __half* xh = (__half*)(smA + KA_XHI);
    __half* xl = (__half*)(smA + KA_XLO);
    uint32_t smb = smem_u32(smA);

    int tid = threadIdx.x;
    int lane = tid & 31;
    int w = tid >> 5;
    int t = blockIdx.y;
    int n0 = blockIdx.x * 64;

    // ---- cp.async W hi/lo tiles (overlaps with x load) ----
#pragma unroll
    for (int r = 0; r < 8; r++) {
        int u = tid + r * 128;
        int c = u >> 4, seg = u & 15;
        uint32_t doff = (uint32_t)(c * 136 + seg * 8) * 2;
        CP_ASYNC16(smb + KA_WHI + doff, g_Whi + c * F + seg * 8);
        CP_ASYNC16(smb + KA_WLO + doff, g_Wlo + c * F + seg * 8);
    }
    CP_COMMIT();

    // ---- load + convert x -> [row][k] hi/lo, stride 136 ----
    {
        int row = tid >> 1, half = tid & 1;
        const float4* xr4 =
            (const float4*)(x + ((size_t)t * N + n0 + row) * F + half * 64);
        __half* xhp = xh + row * 136 + half * 64;
        __half* xlp = xl + row * 136 + half * 64;
#pragma unroll
        for (int j = 0; j < 16; j++) {
            float4 v = xr4[j];
            __half2 h01 = __floats2half2_rn(v.x, v.y);
            __half2 h23 = __floats2half2_rn(v.z, v.w);
            float2 f01 = __half22float2(h01);
            float2 f23 = __half22float2(h23);
            __half2 l01 = __floats2half2_rn(v.x - f01.x, v.y - f01.y);
            __half2 l23 = __floats2half2_rn(v.z - f23.x, v.w - f23.y);
            *(uint32_t*)(xhp + j * 4) = *(uint32_t*)&h01;
            *(uint32_t*)(xhp + j * 4 + 2) = *(uint32_t*)&h23;
            *(uint32_t*)(xlp + j * 4) = *(uint32_t*)&l01;
            *(uint32_t*)(xlp + j * 4 + 2) = *(uint32_t*)&l23;
        }
    }
    CP_WAIT0();
    __syncthreads();

    // ---- MMA: 16 rows per warp, 3 split products ----
    float d[8][4];
#pragma unroll
    for (int nt = 0; nt < 8; nt++)
#pragma unroll
        for (int q = 0; q < 4; q++) d[nt][q] = 0.f;

    uint32_t xhi_b = smb + KA_XHI;
    uint32_t xlo_b = smb + KA_XLO;
    uint32_t whi_b = smb + KA_WHI;
    uint32_t wlo_b = smb + KA_WLO;
    int r0 = w * 16;
    uint32_t rowOffA = (lane & 7) + ((lane >> 3) & 1) * 8;
    uint32_t colOffA = (lane >> 4) * 8;
    uint32_t rowB = ((lane >> 4) << 3) + (lane & 7);
    uint32_t colB = ((lane >> 3) & 1) * 8;

#pragma unroll
    for (int ks = 0; ks < 8; ks++) {
        uint32_t kb = ks * 16;
        uint32_t aoff = ((r0 + rowOffA) * 136 + kb + colOffA) * 2;
        uint32_t ahi[4], alo[4];
        ldsm4(ahi[0], ahi[1], ahi[2], ahi[3], xhi_b + aoff);
        ldsm4(alo[0], alo[1], alo[2], alo[3], xlo_b + aoff);
#pragma unroll
        for (int cg = 0; cg < 4; cg++) {
            uint32_t boff = ((cg * 16 + rowB) * 136 + kb + colB) * 2;
            uint32_t h0, h1, h2, h3, l0, l1, l2, l3;
            ldsm4(h0, h1, h2, h3, whi_b + boff);
            ldsm4(l0, l1, l2, l3, wlo_b + boff);
            mma16816(d[cg * 2], ahi, h0, h1);
            mma16816(d[cg * 2], ahi, l0, l1);
            mma16816(d[cg * 2], alo, h0, h1);
            mma16816(d[cg * 2 + 1], ahi, h2, h3);
            mma16816(d[cg * 2 + 1], ahi, l2, l3);
            mma16816(d[cg * 2 + 1], alo, h2, h3);
        }
    }

    // ---- es/ed from f32 frags ----
    int r1 = r0 + (lane >> 2), r2 = r1 + 8;
    float es1 = 0.f, ed1 = 0.f, es2 = 0.f, ed2 = 0.f;
#pragma unroll
    for (int nt = 0; nt < 8; nt++) {
        int c = nt * 8 + 2 * (lane & 3);
        float a0 = asrc[c], a1 = asrc[c + 1];
        float b0 = adst[c], b1 = adst[c + 1];
        es1 += d[nt][0] * a0 + d[nt][1] * a1;
        ed1 += d[nt][0] * b0 + d[nt][1] * b1;
        es2 += d[nt][2] * a0 + d[nt][3] * a1;
        ed2 += d[nt][2] * b0 + d[nt][3] * b1;
    }
#pragma unroll
    for (int off = 1; off < 4; off <<= 1) {
        es1 += __shfl_xor_sync(0xffffffffu, es1, off);
        ed1 += __shfl_xor_sync(0xffffffffu, ed1, off);
        es2 += __shfl_xor_sync(0xffffffffu, es2, off);
        ed2 += __shfl_xor_sync(0xffffffffu, ed2, off);
    }
    if ((lane & 3) == 0) {
        g_es[t * N + n0 + r1] = es1;
        g_ed[t * N + n0 + r1] = ed1;
        g_es[t * N + n0 + r2] = es2;
        g_ed[t * N + n0 + r2] = ed2;
    }

    // ---- h (hi only) transpose into smem, overlay x region ----
    __syncthreads();
    __half* hh = (__half*)(smA + KA_HHI);
#pragma unroll
    for (int nt = 0; nt < 8; nt++) {
        int c = nt * 8 + 2 * (lane & 3);
        hh[c * 136 + r1] = __float2half_rn(d[nt][0]);
        hh[(c + 1) * 136 + r1] = __float2half_rn(d[nt][1]);
        hh[c * 136 + r2] = __float2half_rn(d[nt][2]);
        hh[(c + 1) * 136 + r2] = __float2half_rn(d[nt][3]);
    }
    __syncthreads();

    // ---- coalesced writeout ----
    __half* dhi = g_hThi + (size_t)t * C * N;
#pragma unroll
    for (int i = 0; i < 4; i++) {
        int u = tid + i * 128;
        int c = u >> 3, seg = u & 7;
        *(uint4*)(dhi + (size_t)c * N + n0 + seg * 8) = *(uint4*)(hh + c * 136 + seg * 8);
    }
}

// ============================================================
// Kernel B: masked-softmax aggregation via fp16 HMMA.
// 512 threads, kt-split warp pairs; 3-deep buffers, ONE sync/chunk.
// ============================================================
#define ADJ_STRIDE 132
#define ADJ_BYTES  33792
#define BB_OFF   0                     // 16384
#define HS_OFF   16384                 // 3 x 9216 = 27648
#define ADJ_OFF  44032                 // 3 x 33792 = 101376
#define RED_OFF  145408                // 2048
#define BIAS_OFF 147456                // 256
#define KB_SMEM  147712
#define DCOMB_OFF ADJ_OFF

__global__ __launch_bounds__(512) void kB(const int* __restrict__ adj,
                                          const float* __restrict__ bias) {
    extern __shared__ __align__(16) char sm[];
    float2* BB = (float2*)(sm + BB_OFF);
    float* red = (float*)(sm + RED_OFF);
    float* bias_s = (float*)(sm + BIAS_OFF);
    uint32_t smb = smem_u32(sm);

    int tid = threadIdx.x;
    int wid = tid >> 5;
    int lane = tid & 31;
    int wl = wid & 7;
    int kh = wid >> 3;
    int t = blockIdx.y;
    int i0 = blockIdx.x * 128;

    const int* abase = adj + (size_t)t * N * N + i0;
    const __half* hhib = g_hThi + (size_t)t * C * N;

    // ---- prologue: chunks 0 and 1 into bufs 0,1 ----
#pragma unroll
    for (int b = 0; b < 2; b++) {
#pragma unroll
        for (int r = 0; r < 4; r++) {
            int u = tid + r * 512;
            int j = u >> 5, off = u & 31;
            CP_ASYNC16(smb + ADJ_OFF + b * ADJ_BYTES + j * 528 + off * 16,
                       abase + (size_t)(b * 64 + j) * N + off * 4);
        }
        int c = tid >> 3, o = tid & 7;
        uint32_t doff = (uint32_t)(c * 72 + o * 8) * 2;
        CP_ASYNC16(smb + HS_OFF + b * 9216 + doff, hhib + (size_t)c * N + b * 64 + o * 8);
        CP_COMMIT();
    }

    if (tid < 16) ((float4*)bias_s)[tid] = ((const float4*)bias)[tid];

    // ---- e_s staging + max + transform ----
    float lmax = -1e30f;
#pragma unroll
    for (int r = 0; r < 4; r++) {
        float v = g_es[t * N + tid + r * 512];
        BB[tid + r * 512].x = v;
        lmax = fmaxf(lmax, v);
    }
    red[tid] = lmax;
    __syncthreads();
    for (int s = 256; s > 0; s >>= 1) {
        if (tid < s) red[tid] = fmaxf(red[tid], red[tid + s]);
        __syncthreads();
    }
    float esmax = red[0];
#pragma unroll
    for (int r = 0; r < 4; r++) {
        int j = tid + r * 512;
        float v = BB[j].x;
        BB[j] = make_float2(__expf(v - esmax), __expf(0.2f * (v - esmax)));
    }

    // ---- per-row constants ----
    int qd = lane >> 2;
    int il1 = wl * 16 + qd;
    int il2 = il1 + 8;
    int gi1 = i0 + il1, gi2 = i0 + il2;
    float ed1 = g_ed[t * N + gi1], ed2 = g_ed[t * N + gi2];
    float xm1 = ed1 + esmax, xm2 = ed2 + esmax;
    float M1 = fmaxf(xm1, 0.2f * xm1), M2 = fmaxf(xm2, 0.2f * xm2);
    float Ai1 = __expf(xm1 - M1), A2i1 = __expf(0.2f * xm1 - M1);
    float Ai2 = __expf(xm2 - M2), A2i2 = __expf(0.2f * xm2 - M2);

    float d[8][4];
#pragma unroll
    for (int nt = 0; nt < 8; nt++)
#pragma unroll
        for (int q = 0; q < 4; q++) d[nt][q] = 0.f;
    float sum1 = 0.f, sum2 = 0.f;

    int q = lane & 3;
    int c0j = 2 * q;
    uint32_t rowa = ((lane >> 4) << 3) + (lane & 7);
    uint32_t cola = ((lane >> 3) & 1) * 8;

    __syncthreads();   // BB ready

#pragma unroll 1
    for (int k = 0; k < 32; k++) {
        int j0 = k * 64;
        int bufk = k % 3;
        if (k < 31) { CP_WAIT1(); } else { CP_WAIT0(); }
        __syncthreads();   // chunk-k data visible; all prior compute done

        // ---- refill buf (k+2)%3 with chunk k+2 ----
        if (k + 2 < 32) {
            int bufn = (k + 2) % 3;
            int jn = j0 + 128;
#pragma unroll
            for (int r = 0; r < 4; r++) {
                int u = tid + r * 512;
                int j = u >> 5, off = u & 31;
                CP_ASYNC16(smb + ADJ_OFF + bufn * ADJ_BYTES + j * 528 + off * 16,
                           abase + (size_t)(jn + j) * N + off * 4);
            }
            int c = tid >> 3, o = tid & 7;
            uint32_t doff = (uint32_t)(c * 72 + o * 8) * 2;
            CP_ASYNC16(smb + HS_OFF + (uint32_t)bufn * 9216 + doff,
                       hhib + (size_t)c * N + jn + o * 8);
            CP_COMMIT();
        }

        const int* adjraw = (const int*)(sm + ADJ_OFF + bufk * ADJ_BYTES);
        uint32_t hhi_u = smb + HS_OFF + (uint32_t)bufk * 9216;
        int sl1 = gi1 - j0, sl2 = gi2 - j0;

#pragma unroll
        for (int ktl = 0; ktl < 2; ktl++) {
            int kt = kh * 2 + ktl;
            int jl = kt * 16 + c0j;

            float p1[4], p2[4];
#pragma unroll
            for (int dIdx = 0; dIdx < 4; dIdx++) {
                int dlt = (dIdx & 1) + (dIdx >> 1) * 8;
                int jj = jl + dlt;
                float2 bb = BB[j0 + jj];
                int v1 = adjraw[jj * ADJ_STRIDE + il1];
                int v2 = adjraw[jj * ADJ_STRIDE + il2];
                bool m1 = (v1 != 0) || (jj == sl1);
                bool m2 = (v2 != 0) || (jj == sl2);
                float pc1 = fmaxf(Ai1 * bb.x, A2i1 * bb.y);
                float pc2 = fmaxf(Ai2 * bb.x, A2i2 * bb.y);
                p1[dIdx] = m1 ? pc1 : 0.f;
                p2[dIdx] = m2 ? pc2 : 0.f;
            }
            sum1 += (p1[0] + p1[1]) + (p1[2] + p1[3]);
            sum2 += (p2[0] + p2[1]) + (p2[2] + p2[3]);

            uint32_t ap[4];
            ap[0] = pack_p(p1[0], p1[1]);
            ap[1] = pack_p(p2[0], p2[1]);
            ap[2] = pack_p(p1[2], p1[3]);
            ap[3] = pack_p(p2[2], p2[3]);

            uint32_t lcol = (uint32_t)(kt * 16) + cola;
#pragma unroll
            for (int cg = 0; cg < 4; cg++) {
                uint32_t roff = ((uint32_t)(cg * 16) + rowa) * 144 + lcol * 2;
                uint32_t h0, h1, h2, h3;
                ldsm4(h0, h1, h2, h3, hhi_u + roff);
                mma16816(d[cg * 2], ap, h0, h1);
                mma16816(d[cg * 2 + 1], ap, h2, h3);
            }
        }
    }

    // ---- combine kt-halves ----
    sum1 += __shfl_xor_sync(0xffffffffu, sum1, 1);
    sum1 += __shfl_xor_sync(0xffffffffu, sum1, 2);
    sum2 += __shfl_xor_sync(0xffffffffu, sum2, 1);
    sum2 += __shfl_xor_sync(0xffffffffu, sum2, 2);

    __syncthreads();
    float* dc = (float*)(sm + DCOMB_OFF);
    float* sums_hi = (float*)(sm + RED_OFF);

    if (kh == 1) {
#pragma unroll
        for (int nt = 0; nt < 8; nt++)
            *(float4*)(dc + wl * 1024 + nt * 128 + lane * 4) =
                make_float4(d[nt][0], d[nt][1], d[nt][2], d[nt][3]);
        if ((lane & 3) == 0) {
            sums_hi[il1] = sum1;
            sums_hi[il2] = sum2;
        }
    }
    __syncthreads();

    if (kh == 0) {
        float st1 = sum1 + sums_hi[il1];
        float st2 = sum2 + sums_hi[il2];
        float s1 = 1.f / st1, s2 = 1.f / st2;

        float* o1 = g_out + ((size_t)t * N + gi1) * C;
        float* o2 = g_out + ((size_t)t * N + gi2) * C;
        int q2 = 2 * q;
#pragma unroll
        for (int nt = 0; nt < 8; nt++) {
            float4 pd = *(const float4*)(dc + wl * 1024 + nt * 128 + lane * 4);
            int c = nt * 8 + q2;
            *(float2*)(o1 + c) = make_float2((d[nt][0] + pd.x) * s1 + bias_s[c],
                                             (d[nt][1] + pd.y) * s1 + bias_s[c + 1]);
            *(float2*)(o2 + c) = make_float2((d[nt][2] + pd.z) * s2 + bias_s[c],
                                             (d[nt][3] + pd.w) * s2 + bias_s[c + 1]);
        }
    }
}

// ============================================================
// Kernel C: inline cosine sims + temporal matvecs.
// 128 nodes/CTA, 4 nodes per thread (weight reads amortized 4x).
// us padded stride 66 (conflict-free; broadcast within dg-groups).
// ============================================================
#define KC_W1 0            // 16384
#define KC_W2 16384        // 16384
#define KC_US 32768        // 128 x 66 float2 = 67584
#define KC_SMEM 100352

__global__ __launch_bounds__(256) void kC(const float* __restrict__ t1w,
                                          const float* __restrict__ t2w,
                                          float* __restrict__ out) {
    extern __shared__ __align__(16) char smC[];
    float* w1 = (float*)(smC + KC_W1);
    float* w2 = (float*)(smC + KC_W2);
    float2* us = (float2*)(smC + KC_US);

    int tid = threadIdx.x;
    int t = blockIdx.y;
    int n0 = blockIdx.x * 128;

#pragma unroll
    for (int r = 0; r < 4; r++) {
        ((float4*)w1)[tid + r * 256] = ((const float4*)t1w)[tid + r * 256];
        ((float4*)w2)[tid + r * 256] = ((const float4*)t2w)[tid + r * 256];
    }

    int nl = tid >> 3;
    int dg = (tid & 7) * 8;

    float curH[4][8];
    unsigned long long acc[4][4];

#pragma unroll
    for (int half = 0; half < 4; half++) {
        int node = nl + half * 32;
        size_t rowo = ((size_t)t * N + n0 + node) * C;
        float cur[8], prv[8], nxt[8];
#pragma unroll
        for (int qq = 0; qq < 2; qq++) {
            float4 v = *(const float4*)(g_out + rowo + dg + qq * 4);
            cur[qq * 4] = v.x; cur[qq * 4 + 1] = v.y;
            cur[qq * 4 + 2] = v.z; cur[qq * 4 + 3] = v.w;
        }
        if (t >= 1) {
#pragma unroll
            for (int qq = 0; qq < 2; qq++) {
                float4 v = *(const float4*)(g_out + rowo - (size_t)N * C + dg + qq * 4);
                prv[qq * 4] = v.x; prv[qq * 4 + 1] = v.y;
                prv[qq * 4 + 2] = v.z; prv[qq * 4 + 3] = v.w;
            }
        } else {
#pragma unroll
            for (int dd = 0; dd < 8; dd++) prv[dd] = 0.f;
        }
        if (t < T - 1) {
#pragma unroll
            for (int qq = 0; qq < 2; qq++) {
                float4 v = *(const float4*)(g_out + rowo + (size_t)N * C + dg + qq * 4);
                nxt[qq * 4] = v.x; nxt[qq * 4 + 1] = v.y;
                nxt[qq * 4 + 2] = v.z; nxt[qq * 4 + 3] = v.w;
            }
        } else {
#pragma unroll
            for (int dd = 0; dd < 8; dd++) nxt[dd] = 0.f;
        }

        float ab = 0.f, bc = 0.f, na = 0.f, nb = 0.f, nc = 0.f;
#pragma unroll
        for (int dd = 0; dd < 8; dd++) {
            ab = fmaf(prv[dd], cur[dd], ab);
            bc = fmaf(cur[dd], nxt[dd], bc);
            na = fmaf(prv[dd], prv[dd], na);
            nb = fmaf(cur[dd], cur[dd], nb);
            nc = fmaf(nxt[dd], nxt[dd], nc);
        }
#pragma unroll
        for (int off = 1; off < 8; off <<= 1) {
            ab += __shfl_xor_sync(0xffffffffu, ab, off);
            bc += __shfl_xor_sync(0xffffffffu, bc, off);
            na += __shfl_xor_sync(0xffffffffu, na, off);
            nb += __shfl_xor_sync(0xffffffffu, nb, off);
            nc += __shfl_xor_sync(0xffffffffu, nc, off);
        }
        float rb = fmaxf(sqrtf(nb), 1e-8f);
        float tem_prev = ab / (fmaxf(sqrtf(na), 1e-8f) * rb);
        float tem_next = bc / (rb * fmaxf(sqrtf(nc), 1e-8f));

        float2* urow = us + node * 66 + dg;
#pragma unroll
        for (int dd = 0; dd < 8; dd++)
            urow[dd] = make_float2(tem_next * nxt[dd], tem_prev * prv[dd]);

#pragma unroll
        for (int dd = 0; dd < 8; dd++) curH[half][dd] = cur[dd];
    }
    __syncthreads();

#pragma unroll
    for (int h = 0; h < 4; h++)
#pragma unroll
        for (int qq = 0; qq < 4; qq++)
            acc[h][qq] = pk2(curH[h][qq * 2], curH[h][qq * 2 + 1]);

    const float2* un0 = us + nl * 66;
#pragma unroll 2
    for (int c = 0; c < C; c++) {
        const ulonglong2* r1 = (const ulonglong2*)(w1 + c * C + dg);
        const ulonglong2* r2 = (const ulonglong2*)(w2 + c * C + dg);
        ulonglong2 wv1 = r1[0], wv1b = r1[1];
        ulonglong2 wv2 = r2[0], wv2b = r2[1];
#pragma unroll
        for (int h = 0; h < 4; h++) {
            float2 u = un0[h * 32 * 66 + c];
            unsigned long long u1 = pk2(u.x, u.x);
            unsigned long long u2 = pk2(u.y, u.y);
            fma2(acc[h][0], wv1.x, u1);
            fma2(acc[h][1], wv1.y, u1);
            fma2(acc[h][2], wv1b.x, u1);
            fma2(acc[h][3], wv1b.y, u1);
            fma2(acc[h][0], wv2.x, u2);
            fma2(acc[h][1], wv2.y, u2);
            fma2(acc[h][2], wv2b.x, u2);
            fma2(acc[h][3], wv2b.y, u2);
        }
    }

#pragma unroll
    for (int h = 0; h < 4; h++) {
        float r[8];
#pragma unroll
        for (int qq = 0; qq < 4; qq++) upk2(acc[h][qq], r[qq * 2], r[qq * 2 + 1]);
        size_t rowo = ((size_t)t * N + n0 + nl + h * 32) * C;
#pragma unroll
        for (int qq = 0; qq < 2; qq++) {
            *(float4*)(out + rowo + dg + qq * 4) =
                make_float4(r[qq * 4], r[qq * 4 + 1], r[qq * 4 + 2], r[qq * 4 + 3]);
        }
    }
}

// ============================================================
extern "C" void kernel_launch(void* const* d_in, const int* in_sizes, int n_in,
                              void* d_out, int out_size) {
    const float* x = (const float*)d_in[0];
    const int* adj = (const int*)d_in[1];
    const float* W = (const float*)d_in[2];
    const float* asrc = (const float*)d_in[3];
    const float* adst = (const float*)d_in[4];
    const float* bias = (const float*)d_in[5];
    const float* t1w = (const float*)d_in[6];
    const float* t2w = (const float*)d_in[7];
    float* out = (float*)d_out;

    cudaFuncSetAttribute(kA, cudaFuncAttributeMaxDynamicSharedMemorySize, KA_SMEM);
    cudaFuncSetAttribute(kB, cudaFuncAttributeMaxDynamicSharedMemorySize, KB_SMEM);
    cudaFuncSetAttribute(kC, cudaFuncAttributeMaxDynamicSharedMemorySize, KC_SMEM);

    kW<<<1, 256>>>(W);
    kA<<<dim3(N / 64, T), 128, KA_SMEM>>>(x, asrc, adst);
    kB<<<dim3(N / 128, T), 512, KB_SMEM>>>(adj, bias);
    kC<<<dim3(N / 128, T), 256, KC_SMEM>>>(t1w, t2w, out);
}